// round 1
// baseline (speedup 1.0000x reference)
#include <cuda_runtime.h>
#include <math.h>

#define T_TOK   1024
#define DIM     512
#define INTER   256
#define SINTER  1024
#define NEXP    64
#define TOPK    6

// ---------------- scratch (device globals; no allocation) ----------------
__device__ int   g_topk_idx[T_TOK * TOPK];
__device__ float g_topk_w[T_TOK * TOPK];
__device__ int   g_counts[NEXP];
__device__ int   g_tok[NEXP * T_TOK];
__device__ int   g_tslot[NEXP * T_TOK];
__device__ float g_tw[NEXP * T_TOK];
__device__ float g_contrib[T_TOK * TOPK * DIM];   // 12.6 MB
__device__ float g_hs[T_TOK * SINTER];            // 4 MB

// ---------------- 1. router: scores -> top6 -> softmax ----------------
__global__ __launch_bounds__(64) void router_kernel(
    const float* __restrict__ x, const float* __restrict__ wg)
{
    int t   = blockIdx.x;
    int tid = threadIdx.x;            // 0..63, one expert per thread
    __shared__ float xs[DIM];
    __shared__ float sc[NEXP];

    for (int i = tid; i < DIM; i += 64) xs[i] = x[t * DIM + i];
    __syncthreads();

    float acc = 0.f;
    const float4* wr = (const float4*)(wg + (size_t)tid * DIM);
    #pragma unroll 4
    for (int d4 = 0; d4 < DIM / 4; d4++) {
        float4 w  = wr[d4];
        float4 xv = *(const float4*)&xs[d4 * 4];
        acc = fmaf(w.x, xv.x, fmaf(w.y, xv.y, fmaf(w.z, xv.z, fmaf(w.w, xv.w, acc))));
    }
    sc[tid] = acc;
    __syncthreads();

    if (tid == 0) {
        float vals[TOPK]; int idx[TOPK];
        for (int k = 0; k < TOPK; k++) {
            float best = -INFINITY; int bi = 0;
            for (int e = 0; e < NEXP; e++) {
                if (sc[e] > best) { best = sc[e]; bi = e; }   // strict > == lowest-index tie-break
            }
            vals[k] = best; idx[k] = bi; sc[bi] = -INFINITY;
        }
        float mx = vals[0];
        float w6[TOPK]; float sum = 0.f;
        #pragma unroll
        for (int k = 0; k < TOPK; k++) { w6[k] = __expf(vals[k] - mx); sum += w6[k]; }
        float inv = 1.f / sum;
        #pragma unroll
        for (int k = 0; k < TOPK; k++) {
            g_topk_idx[t * TOPK + k] = idx[k];
            g_topk_w[t * TOPK + k]   = w6[k] * inv;
        }
    }
}

// ---------------- 2. deterministic per-expert token lists (prefix scan) ----------------
__global__ __launch_bounds__(1024) void group_kernel()
{
    int e = blockIdx.x;
    int t = threadIdx.x;              // token id
    int slot = -1;
    #pragma unroll
    for (int k = 0; k < TOPK; k++)
        if (g_topk_idx[t * TOPK + k] == e) slot = k;
    int flag = (slot >= 0) ? 1 : 0;

    __shared__ int sc[T_TOK];
    sc[t] = flag;
    __syncthreads();
    for (int off = 1; off < T_TOK; off <<= 1) {
        int v = (t >= off) ? sc[t - off] : 0;
        __syncthreads();
        sc[t] += v;
        __syncthreads();
    }
    if (flag) {
        int pos = sc[t] - 1;          // inclusive -> exclusive
        g_tok[e * T_TOK + pos]   = t;
        g_tslot[e * T_TOK + pos] = slot;
        g_tw[e * T_TOK + pos]    = g_topk_w[t * TOPK + slot];
    }
    if (t == T_TOK - 1) g_counts[e] = sc[T_TOK - 1];
}

// ---------------- 3. routed experts: SwiGLU + down-proj per 16-token tile ----------------
__global__ __launch_bounds__(256) void routed_kernel(
    const float* __restrict__ x,
    const float* __restrict__ w1,
    const float* __restrict__ w2,
    const float* __restrict__ w3)
{
    const int e   = blockIdx.y;
    const int cnt = g_counts[e];
    const int m0  = blockIdx.x * 16;
    if (m0 >= cnt) return;
    const int mr  = min(16, cnt - m0);
    const int tid = threadIdx.x;

    __shared__ float xs[16 * DIM];    // 32 KB, reused as h-tile [16][256] in phase B
    __shared__ int   s_tok[16];
    __shared__ int   s_slot[16];
    __shared__ float s_w[16];

    if (tid < 16) {
        int mm = (tid < mr) ? tid : 0;
        s_tok[tid]  = g_tok[e * T_TOK + m0 + mm];
        s_slot[tid] = g_tslot[e * T_TOK + m0 + mm];
        s_w[tid]    = g_tw[e * T_TOK + m0 + mm];
    }
    __syncthreads();

    for (int idx = tid; idx < 16 * DIM; idx += 256) {
        int m = idx >> 9, d = idx & (DIM - 1);
        xs[idx] = x[(size_t)s_tok[m] * DIM + d];
    }
    __syncthreads();

    // ---- phase A: h[m][i] for i = tid ----
    float acc1[16], acc3[16];
    #pragma unroll
    for (int m = 0; m < 16; m++) { acc1[m] = 0.f; acc3[m] = 0.f; }

    const float4* w1v = (const float4*)(w1 + ((size_t)e * INTER + tid) * DIM);
    const float4* w3v = (const float4*)(w3 + ((size_t)e * INTER + tid) * DIM);
    for (int d4 = 0; d4 < DIM / 4; d4++) {
        float4 a = w1v[d4];
        float4 b = w3v[d4];
        #pragma unroll
        for (int m = 0; m < 16; m++) {
            float4 xv = *(const float4*)&xs[m * DIM + d4 * 4];
            acc1[m] = fmaf(a.x, xv.x, fmaf(a.y, xv.y, fmaf(a.z, xv.z, fmaf(a.w, xv.w, acc1[m]))));
            acc3[m] = fmaf(b.x, xv.x, fmaf(b.y, xv.y, fmaf(b.z, xv.z, fmaf(b.w, xv.w, acc3[m]))));
        }
    }
    __syncthreads();                  // done reading xs

    float* hs = xs;                   // reuse smem: [16][256]
    #pragma unroll
    for (int m = 0; m < 16; m++) {
        float v = acc1[m];
        float s = v / (1.f + __expf(-v));        // silu
        hs[m * INTER + tid] = s * acc3[m];
    }
    __syncthreads();

    // ---- phase B: y[m][d] = sum_i h[m][i] * w2[e][i][d]; d = tid, tid+256 ----
    const float* w2e = w2 + (size_t)e * INTER * DIM;
    for (int half = 0; half < 2; half++) {
        float acc[8][2];
        #pragma unroll
        for (int m = 0; m < 8; m++) { acc[m][0] = 0.f; acc[m][1] = 0.f; }

        for (int i4 = 0; i4 < INTER / 4; i4++) {
            float wa[4], wb[4];
            #pragma unroll
            for (int u = 0; u < 4; u++) {
                wa[u] = w2e[(i4 * 4 + u) * DIM + tid];
                wb[u] = w2e[(i4 * 4 + u) * DIM + tid + 256];
            }
            #pragma unroll
            for (int m = 0; m < 8; m++) {
                float4 h = *(const float4*)&hs[(half * 8 + m) * INTER + i4 * 4];
                acc[m][0] = fmaf(h.x, wa[0], fmaf(h.y, wa[1], fmaf(h.z, wa[2], fmaf(h.w, wa[3], acc[m][0]))));
                acc[m][1] = fmaf(h.x, wb[0], fmaf(h.y, wb[1], fmaf(h.z, wb[2], fmaf(h.w, wb[3], acc[m][1]))));
            }
        }
        #pragma unroll
        for (int m = 0; m < 8; m++) {
            int mm = half * 8 + m;
            if (mm < mr) {
                int   t = s_tok[mm];
                int   s = s_slot[mm];
                float w = s_w[mm];
                size_t base = ((size_t)(t * TOPK + s)) * DIM;
                g_contrib[base + tid]       = w * acc[m][0];
                g_contrib[base + tid + 256] = w * acc[m][1];
            }
        }
    }
}

// ---------------- 4. shared expert phase 1: H = silu(x Wg^T) * (x Wu^T) ----------------
__global__ __launch_bounds__(256) void shared1_kernel(
    const float* __restrict__ x,
    const float* __restrict__ wsg,
    const float* __restrict__ wsu)
{
    const int t0  = blockIdx.x * 16;
    const int tid = threadIdx.x;
    const int j   = blockIdx.y * 256 + tid;

    __shared__ float xs[16 * DIM];
    for (int idx = tid; idx < 16 * DIM; idx += 256) {
        xs[idx] = x[(size_t)(t0 + (idx >> 9)) * DIM + (idx & (DIM - 1))];
    }
    __syncthreads();

    float acc1[16], acc3[16];
    #pragma unroll
    for (int m = 0; m < 16; m++) { acc1[m] = 0.f; acc3[m] = 0.f; }

    const float4* wg4 = (const float4*)(wsg + (size_t)j * DIM);
    const float4* wu4 = (const float4*)(wsu + (size_t)j * DIM);
    for (int d4 = 0; d4 < DIM / 4; d4++) {
        float4 a = wg4[d4];
        float4 b = wu4[d4];
        #pragma unroll
        for (int m = 0; m < 16; m++) {
            float4 xv = *(const float4*)&xs[m * DIM + d4 * 4];
            acc1[m] = fmaf(a.x, xv.x, fmaf(a.y, xv.y, fmaf(a.z, xv.z, fmaf(a.w, xv.w, acc1[m]))));
            acc3[m] = fmaf(b.x, xv.x, fmaf(b.y, xv.y, fmaf(b.z, xv.z, fmaf(b.w, xv.w, acc3[m]))));
        }
    }
    #pragma unroll
    for (int m = 0; m < 16; m++) {
        float v = acc1[m];
        float s = v / (1.f + __expf(-v));
        g_hs[(size_t)(t0 + m) * SINTER + j] = s * acc3[m];
    }
}

// ---------------- 5. final: out = H * Wsd^T + sum_k contrib ----------------
__global__ __launch_bounds__(256) void final_kernel(
    const float* __restrict__ wsd, float* __restrict__ out)
{
    const int t0  = blockIdx.x * 16;
    const int tid = threadIdx.x;
    __shared__ float hstile[16 * 256];

    for (int half = 0; half < 2; half++) {
        float acc[8][2];
        #pragma unroll
        for (int m = 0; m < 8; m++) { acc[m][0] = 0.f; acc[m][1] = 0.f; }

        for (int jt = 0; jt < 4; jt++) {
            __syncthreads();
            for (int idx = tid; idx < 16 * 256; idx += 256) {
                int m = idx >> 8, c = idx & 255;
                hstile[idx] = g_hs[(size_t)(t0 + m) * SINTER + jt * 256 + c];
            }
            __syncthreads();

            const float4* wa4 = (const float4*)(wsd + (size_t)tid * SINTER + jt * 256);
            const float4* wb4 = (const float4*)(wsd + (size_t)(tid + 256) * SINTER + jt * 256);
            for (int i4 = 0; i4 < 64; i4++) {
                float4 wa = wa4[i4];
                float4 wb = wb4[i4];
                #pragma unroll
                for (int m = 0; m < 8; m++) {
                    float4 h = *(const float4*)&hstile[(half * 8 + m) * 256 + i4 * 4];
                    acc[m][0] = fmaf(h.x, wa.x, fmaf(h.y, wa.y, fmaf(h.z, wa.z, fmaf(h.w, wa.w, acc[m][0]))));
                    acc[m][1] = fmaf(h.x, wb.x, fmaf(h.y, wb.y, fmaf(h.z, wb.z, fmaf(h.w, wb.w, acc[m][1]))));
                }
            }
        }
        #pragma unroll
        for (int m = 0; m < 8; m++) {
            int t = t0 + half * 8 + m;
            float c0 = acc[m][0], c1 = acc[m][1];
            #pragma unroll
            for (int k = 0; k < TOPK; k++) {
                size_t base = ((size_t)(t * TOPK + k)) * DIM;
                c0 += g_contrib[base + tid];
                c1 += g_contrib[base + tid + 256];
            }
            out[(size_t)t * DIM + tid]       = c0;
            out[(size_t)t * DIM + tid + 256] = c1;
        }
    }
}

// ---------------- launcher ----------------
extern "C" void kernel_launch(void* const* d_in, const int* in_sizes, int n_in,
                              void* d_out, int out_size)
{
    const float* x    = (const float*)d_in[0];
    const float* wg   = (const float*)d_in[1];
    const float* w1   = (const float*)d_in[2];
    const float* w2   = (const float*)d_in[3];
    const float* w3   = (const float*)d_in[4];
    const float* wsg  = (const float*)d_in[5];
    const float* wsu  = (const float*)d_in[6];
    const float* wsd  = (const float*)d_in[7];
    float* out = (float*)d_out;

    router_kernel<<<T_TOK, 64>>>(x, wg);
    group_kernel<<<NEXP, 1024>>>();
    routed_kernel<<<dim3(T_TOK / 16, NEXP), 256>>>(x, w1, w2, w3);
    shared1_kernel<<<dim3(T_TOK / 16, SINTER / 256), 256>>>(x, wsg, wsu);
    final_kernel<<<T_TOK / 16, 256>>>(wsd, out);
}

// round 2
// speedup vs baseline: 1.0596x; 1.0596x over previous
#include <cuda_runtime.h>
#include <math.h>
#include <stdint.h>

#define T_TOK   1024
#define DIM     512
#define INTER   256
#define SINTER  1024
#define NEXP    64
#define TOPK    6

#define XS_STRIDE 72     // 64 cols + pad
#define HS_STRIDE 264    // 256 cols + pad

// ---------------- scratch (device globals; no allocation) ----------------
__device__ int   g_topk_idx[T_TOK * TOPK];
__device__ float g_topk_w[T_TOK * TOPK];
__device__ int   g_counts[NEXP];
__device__ int   g_tok[NEXP * T_TOK];
__device__ int   g_tslot[NEXP * T_TOK];
__device__ float g_tw[NEXP * T_TOK];
__device__ float g_contrib[T_TOK * TOPK * DIM];   // 12.6 MB
__device__ float g_hs[T_TOK * SINTER];            // 4 MB

// ---------------- tf32 helpers ----------------
__device__ __forceinline__ uint32_t f2tf32(float v) {
    uint32_t r; asm("cvt.rna.tf32.f32 %0, %1;" : "=r"(r) : "f"(v)); return r;
}
__device__ __forceinline__ void mma8(float c[4], const uint32_t a[4],
                                     uint32_t b0, uint32_t b1) {
    asm volatile(
        "mma.sync.aligned.m16n8k8.row.col.f32.tf32.tf32.f32 "
        "{%0,%1,%2,%3}, {%4,%5,%6,%7}, {%8,%9}, {%0,%1,%2,%3};"
        : "+f"(c[0]), "+f"(c[1]), "+f"(c[2]), "+f"(c[3])
        : "r"(a[0]), "r"(a[1]), "r"(a[2]), "r"(a[3]), "r"(b0), "r"(b1));
}

// ---------------- 1. router ----------------
__global__ __launch_bounds__(64) void router_kernel(
    const float* __restrict__ x, const float* __restrict__ wg)
{
    int t   = blockIdx.x;
    int tid = threadIdx.x;
    __shared__ float xs[DIM];
    __shared__ float sc[NEXP];

    for (int i = tid; i < DIM; i += 64) xs[i] = x[t * DIM + i];
    __syncthreads();

    float acc = 0.f;
    const float4* wr = (const float4*)(wg + (size_t)tid * DIM);
    #pragma unroll 4
    for (int d4 = 0; d4 < DIM / 4; d4++) {
        float4 w  = wr[d4];
        float4 xv = *(const float4*)&xs[d4 * 4];
        acc = fmaf(w.x, xv.x, fmaf(w.y, xv.y, fmaf(w.z, xv.z, fmaf(w.w, xv.w, acc))));
    }
    sc[tid] = acc;
    __syncthreads();

    if (tid == 0) {
        float vals[TOPK]; int idx[TOPK];
        for (int k = 0; k < TOPK; k++) {
            float best = -INFINITY; int bi = 0;
            for (int e = 0; e < NEXP; e++)
                if (sc[e] > best) { best = sc[e]; bi = e; }
            vals[k] = best; idx[k] = bi; sc[bi] = -INFINITY;
        }
        float mx = vals[0];
        float w6[TOPK]; float sum = 0.f;
        #pragma unroll
        for (int k = 0; k < TOPK; k++) { w6[k] = __expf(vals[k] - mx); sum += w6[k]; }
        float inv = 1.f / sum;
        #pragma unroll
        for (int k = 0; k < TOPK; k++) {
            g_topk_idx[t * TOPK + k] = idx[k];
            g_topk_w[t * TOPK + k]   = w6[k] * inv;
        }
    }
}

// ---------------- 2. deterministic grouping ----------------
__global__ __launch_bounds__(1024) void group_kernel()
{
    int e = blockIdx.x;
    int t = threadIdx.x;
    int slot = -1;
    #pragma unroll
    for (int k = 0; k < TOPK; k++)
        if (g_topk_idx[t * TOPK + k] == e) slot = k;
    int flag = (slot >= 0) ? 1 : 0;

    __shared__ int sc[T_TOK];
    sc[t] = flag;
    __syncthreads();
    for (int off = 1; off < T_TOK; off <<= 1) {
        int v = (t >= off) ? sc[t - off] : 0;
        __syncthreads();
        sc[t] += v;
        __syncthreads();
    }
    if (flag) {
        int pos = sc[t] - 1;
        g_tok[e * T_TOK + pos]   = t;
        g_tslot[e * T_TOK + pos] = slot;
        g_tw[e * T_TOK + pos]    = g_topk_w[t * TOPK + slot];
    }
    if (t == T_TOK - 1) g_counts[e] = sc[T_TOK - 1];
}

// ---------------- A-fragment loader (rows rt*16+gid/+8, cols ks*8+l4/+4) ----
__device__ __forceinline__ void load_afrag(const float* base, int stride,
                                           int gid, int l4, int ks,
                                           uint32_t a[4][4]) {
    #pragma unroll
    for (int rt = 0; rt < 4; rt++) {
        int r0 = rt * 16 + gid, r1 = r0 + 8;
        int c0 = ks * 8 + l4;
        a[rt][0] = __float_as_uint(base[r0 * stride + c0]);
        a[rt][1] = __float_as_uint(base[r1 * stride + c0]);
        a[rt][2] = __float_as_uint(base[r0 * stride + c0 + 4]);
        a[rt][3] = __float_as_uint(base[r1 * stride + c0 + 4]);
    }
}

// ---------------- 3. routed experts (MMA, 3xTF32) ----------------
__global__ __launch_bounds__(256, 1) void routed_mma(
    const float* __restrict__ x,
    const float* __restrict__ w1,
    const float* __restrict__ w2,
    const float* __restrict__ w3)
{
    extern __shared__ float sm[];
    float* xs_hi = sm;                        // 64*72
    float* xs_lo = xs_hi + 64 * XS_STRIDE;
    float* hs_hi = xs_lo + 64 * XS_STRIDE;    // 64*264
    float* hs_lo = hs_hi + 64 * HS_STRIDE;

    const int e   = blockIdx.y;
    const int cnt = g_counts[e];
    const int m0  = blockIdx.x * 64;
    if (m0 >= cnt) return;
    const int mr  = min(64, cnt - m0);

    const int tid  = threadIdx.x;
    const int wid  = tid >> 5;
    const int lane = tid & 31;
    const int gid  = lane >> 2;
    const int l4   = lane & 3;

    __shared__ int   s_tok[64];
    __shared__ int   s_slot[64];
    __shared__ float s_w[64];
    if (tid < 64) {
        int mm = (tid < mr) ? tid : 0;
        s_tok[tid]  = g_tok[e * T_TOK + m0 + mm];
        s_slot[tid] = g_tslot[e * T_TOK + m0 + mm];
        s_w[tid]    = g_tw[e * T_TOK + m0 + mm];
    }

    // ---- phase A: h = silu(x@w1^T) * (x@w3^T), two passes over weights ----
    for (int p = 0; p < 2; p++) {
        const float* Wb = (p ? w3 : w1) + (size_t)e * INTER * DIM;
        float c[4][4][4];
        #pragma unroll
        for (int i = 0; i < 4; i++)
            #pragma unroll
            for (int j = 0; j < 4; j++)
                #pragma unroll
                for (int q = 0; q < 4; q++) c[i][j][q] = 0.f;

        for (int kb = 0; kb < DIM; kb += 64) {
            __syncthreads();
            for (int idx = tid; idx < 64 * 64; idx += 256) {
                int m = idx >> 6, kk = idx & 63;
                float v = x[(size_t)s_tok[m] * DIM + kb + kk];
                uint32_t h = f2tf32(v);
                xs_hi[m * XS_STRIDE + kk] = __uint_as_float(h);
                xs_lo[m * XS_STRIDE + kk] = v - __uint_as_float(h);
            }
            __syncthreads();
            #pragma unroll
            for (int ks = 0; ks < 8; ks++) {
                uint32_t ah[4][4], al[4][4];
                load_afrag(xs_hi, XS_STRIDE, gid, l4, ks, ah);
                load_afrag(xs_lo, XS_STRIDE, gid, l4, ks, al);
                #pragma unroll
                for (int ct = 0; ct < 4; ct++) {
                    int n = wid * 32 + ct * 8 + gid;
                    const float* wp = Wb + (size_t)n * DIM + kb + ks * 8 + l4;
                    float b0v = wp[0], b1v = wp[4];
                    uint32_t bh0 = f2tf32(b0v), bh1 = f2tf32(b1v);
                    uint32_t bl0 = __float_as_uint(b0v - __uint_as_float(bh0));
                    uint32_t bl1 = __float_as_uint(b1v - __uint_as_float(bh1));
                    #pragma unroll
                    for (int rt = 0; rt < 4; rt++) {
                        mma8(c[rt][ct], ah[rt], bh0, bh1);
                        mma8(c[rt][ct], ah[rt], bl0, bl1);
                        mma8(c[rt][ct], al[rt], bh0, bh1);
                    }
                }
            }
        }
        // epilogue (same-thread positions across passes; no sync needed here)
        #pragma unroll
        for (int rt = 0; rt < 4; rt++) {
            #pragma unroll
            for (int ct = 0; ct < 4; ct++) {
                int col = wid * 32 + ct * 8 + 2 * l4;
                int r0 = rt * 16 + gid, r1 = r0 + 8;
                if (p == 0) {
                    hs_hi[r0 * HS_STRIDE + col]     = c[rt][ct][0];
                    hs_hi[r0 * HS_STRIDE + col + 1] = c[rt][ct][1];
                    hs_hi[r1 * HS_STRIDE + col]     = c[rt][ct][2];
                    hs_hi[r1 * HS_STRIDE + col + 1] = c[rt][ct][3];
                } else {
                    #pragma unroll
                    for (int q = 0; q < 4; q++) {
                        int rr  = (q < 2) ? r0 : r1;
                        int ccl = col + (q & 1);
                        float a1 = hs_hi[rr * HS_STRIDE + ccl];
                        float sv = (a1 / (1.f + __expf(-a1))) * c[rt][ct][q];
                        uint32_t hv = f2tf32(sv);
                        hs_hi[rr * HS_STRIDE + ccl] = __uint_as_float(hv);
                        hs_lo[rr * HS_STRIDE + ccl] = sv - __uint_as_float(hv);
                    }
                }
            }
        }
    }
    __syncthreads();   // h tile visible to all warps

    // ---- phase B: y = h @ w2^T  (K=256, N=512 in two passes) ----
    const float* W2e = w2 + (size_t)e * INTER * DIM;
    for (int np = 0; np < 2; np++) {
        float c[4][4][4];
        #pragma unroll
        for (int i = 0; i < 4; i++)
            #pragma unroll
            for (int j = 0; j < 4; j++)
                #pragma unroll
                for (int q = 0; q < 4; q++) c[i][j][q] = 0.f;

        #pragma unroll 2
        for (int ks = 0; ks < INTER / 8; ks++) {
            uint32_t ah[4][4], al[4][4];
            load_afrag(hs_hi, HS_STRIDE, gid, l4, ks, ah);
            load_afrag(hs_lo, HS_STRIDE, gid, l4, ks, al);
            #pragma unroll
            for (int ct = 0; ct < 4; ct++) {
                int n = np * 256 + wid * 32 + ct * 8 + gid;
                int k = ks * 8 + l4;
                float b0v = W2e[(size_t)k * DIM + n];
                float b1v = W2e[(size_t)(k + 4) * DIM + n];
                uint32_t bh0 = f2tf32(b0v), bh1 = f2tf32(b1v);
                uint32_t bl0 = __float_as_uint(b0v - __uint_as_float(bh0));
                uint32_t bl1 = __float_as_uint(b1v - __uint_as_float(bh1));
                #pragma unroll
                for (int rt = 0; rt < 4; rt++) {
                    mma8(c[rt][ct], ah[rt], bh0, bh1);
                    mma8(c[rt][ct], ah[rt], bl0, bl1);
                    mma8(c[rt][ct], al[rt], bh0, bh1);
                }
            }
        }
        // write scaled contributions
        #pragma unroll
        for (int rt = 0; rt < 4; rt++) {
            #pragma unroll
            for (int ct = 0; ct < 4; ct++) {
                int col = np * 256 + wid * 32 + ct * 8 + 2 * l4;
                int r0 = rt * 16 + gid, r1 = r0 + 8;
                if (r0 < mr) {
                    size_t base = ((size_t)(s_tok[r0] * TOPK + s_slot[r0])) * DIM + col;
                    float w = s_w[r0];
                    g_contrib[base]     = w * c[rt][ct][0];
                    g_contrib[base + 1] = w * c[rt][ct][1];
                }
                if (r1 < mr) {
                    size_t base = ((size_t)(s_tok[r1] * TOPK + s_slot[r1])) * DIM + col;
                    float w = s_w[r1];
                    g_contrib[base]     = w * c[rt][ct][2];
                    g_contrib[base + 1] = w * c[rt][ct][3];
                }
            }
        }
    }
}

// ---------------- 4. shared expert up: H = silu(xWg^T)*(xWu^T) ----------------
__global__ __launch_bounds__(256, 1) void shared1_mma(
    const float* __restrict__ x,
    const float* __restrict__ wsg,
    const float* __restrict__ wsu)
{
    extern __shared__ float sm[];
    float* xs_hi = sm;
    float* xs_lo = xs_hi + 64 * XS_STRIDE;
    float* hraw  = xs_lo + 64 * XS_STRIDE;   // 64*264 raw gate values

    const int m0 = blockIdx.x * 64;
    const int nb = blockIdx.y * 256;

    const int tid  = threadIdx.x;
    const int wid  = tid >> 5;
    const int lane = tid & 31;
    const int gid  = lane >> 2;
    const int l4   = lane & 3;

    for (int p = 0; p < 2; p++) {
        const float* Wb = p ? wsu : wsg;
        float c[4][4][4];
        #pragma unroll
        for (int i = 0; i < 4; i++)
            #pragma unroll
            for (int j = 0; j < 4; j++)
                #pragma unroll
                for (int q = 0; q < 4; q++) c[i][j][q] = 0.f;

        for (int kb = 0; kb < DIM; kb += 64) {
            __syncthreads();
            for (int idx = tid; idx < 64 * 64; idx += 256) {
                int m = idx >> 6, kk = idx & 63;
                float v = x[(size_t)(m0 + m) * DIM + kb + kk];
                uint32_t h = f2tf32(v);
                xs_hi[m * XS_STRIDE + kk] = __uint_as_float(h);
                xs_lo[m * XS_STRIDE + kk] = v - __uint_as_float(h);
            }
            __syncthreads();
            #pragma unroll
            for (int ks = 0; ks < 8; ks++) {
                uint32_t ah[4][4], al[4][4];
                load_afrag(xs_hi, XS_STRIDE, gid, l4, ks, ah);
                load_afrag(xs_lo, XS_STRIDE, gid, l4, ks, al);
                #pragma unroll
                for (int ct = 0; ct < 4; ct++) {
                    int n = nb + wid * 32 + ct * 8 + gid;
                    const float* wp = Wb + (size_t)n * DIM + kb + ks * 8 + l4;
                    float b0v = wp[0], b1v = wp[4];
                    uint32_t bh0 = f2tf32(b0v), bh1 = f2tf32(b1v);
                    uint32_t bl0 = __float_as_uint(b0v - __uint_as_float(bh0));
                    uint32_t bl1 = __float_as_uint(b1v - __uint_as_float(bh1));
                    #pragma unroll
                    for (int rt = 0; rt < 4; rt++) {
                        mma8(c[rt][ct], ah[rt], bh0, bh1);
                        mma8(c[rt][ct], ah[rt], bl0, bl1);
                        mma8(c[rt][ct], al[rt], bh0, bh1);
                    }
                }
            }
        }
        #pragma unroll
        for (int rt = 0; rt < 4; rt++) {
            #pragma unroll
            for (int ct = 0; ct < 4; ct++) {
                int col = wid * 32 + ct * 8 + 2 * l4;
                int r0 = rt * 16 + gid, r1 = r0 + 8;
                if (p == 0) {
                    hraw[r0 * HS_STRIDE + col]     = c[rt][ct][0];
                    hraw[r0 * HS_STRIDE + col + 1] = c[rt][ct][1];
                    hraw[r1 * HS_STRIDE + col]     = c[rt][ct][2];
                    hraw[r1 * HS_STRIDE + col + 1] = c[rt][ct][3];
                } else {
                    #pragma unroll
                    for (int q = 0; q < 4; q++) {
                        int rr  = (q < 2) ? r0 : r1;
                        int ccl = col + (q & 1);
                        float a1 = hraw[rr * HS_STRIDE + ccl];
                        float sv = (a1 / (1.f + __expf(-a1))) * c[rt][ct][q];
                        g_hs[(size_t)(m0 + rr) * SINTER + nb + ccl] = sv;
                    }
                }
            }
        }
    }
}

// ---------------- 5. final: out = H @ Wsd^T + routed contribs ----------------
__global__ __launch_bounds__(256, 1) void final_mma(
    const float* __restrict__ wsd, float* __restrict__ out)
{
    extern __shared__ float sm[];
    float* xs_hi = sm;
    float* xs_lo = xs_hi + 64 * XS_STRIDE;

    const int m0 = blockIdx.x * 64;
    const int tid  = threadIdx.x;
    const int wid  = tid >> 5;
    const int lane = tid & 31;
    const int gid  = lane >> 2;
    const int l4   = lane & 3;

    for (int np = 0; np < 2; np++) {
        float c[4][4][4];
        #pragma unroll
        for (int i = 0; i < 4; i++)
            #pragma unroll
            for (int j = 0; j < 4; j++)
                #pragma unroll
                for (int q = 0; q < 4; q++) c[i][j][q] = 0.f;

        for (int kb = 0; kb < SINTER; kb += 64) {
            __syncthreads();
            for (int idx = tid; idx < 64 * 64; idx += 256) {
                int m = idx >> 6, kk = idx & 63;
                float v = g_hs[(size_t)(m0 + m) * SINTER + kb + kk];
                uint32_t h = f2tf32(v);
                xs_hi[m * XS_STRIDE + kk] = __uint_as_float(h);
                xs_lo[m * XS_STRIDE + kk] = v - __uint_as_float(h);
            }
            __syncthreads();
            #pragma unroll
            for (int ks = 0; ks < 8; ks++) {
                uint32_t ah[4][4], al[4][4];
                load_afrag(xs_hi, XS_STRIDE, gid, l4, ks, ah);
                load_afrag(xs_lo, XS_STRIDE, gid, l4, ks, al);
                #pragma unroll
                for (int ct = 0; ct < 4; ct++) {
                    int n = np * 256 + wid * 32 + ct * 8 + gid;
                    const float* wp = wsd + (size_t)n * SINTER + kb + ks * 8 + l4;
                    float b0v = wp[0], b1v = wp[4];
                    uint32_t bh0 = f2tf32(b0v), bh1 = f2tf32(b1v);
                    uint32_t bl0 = __float_as_uint(b0v - __uint_as_float(bh0));
                    uint32_t bl1 = __float_as_uint(b1v - __uint_as_float(bh1));
                    #pragma unroll
                    for (int rt = 0; rt < 4; rt++) {
                        mma8(c[rt][ct], ah[rt], bh0, bh1);
                        mma8(c[rt][ct], ah[rt], bl0, bl1);
                        mma8(c[rt][ct], al[rt], bh0, bh1);
                    }
                }
            }
        }
        // epilogue: add the 6 routed contributions, write out
        #pragma unroll
        for (int rt = 0; rt < 4; rt++) {
            #pragma unroll
            for (int ct = 0; ct < 4; ct++) {
                int col = np * 256 + wid * 32 + ct * 8 + 2 * l4;
                int r0 = m0 + rt * 16 + gid, r1 = r0 + 8;
                float v0 = c[rt][ct][0], v1 = c[rt][ct][1];
                float v2 = c[rt][ct][2], v3 = c[rt][ct][3];
                #pragma unroll
                for (int kk = 0; kk < TOPK; kk++) {
                    float2 p0 = *(const float2*)&g_contrib[((size_t)(r0 * TOPK + kk)) * DIM + col];
                    float2 p1 = *(const float2*)&g_contrib[((size_t)(r1 * TOPK + kk)) * DIM + col];
                    v0 += p0.x; v1 += p0.y;
                    v2 += p1.x; v3 += p1.y;
                }
                out[(size_t)r0 * DIM + col]     = v0;
                out[(size_t)r0 * DIM + col + 1] = v1;
                out[(size_t)r1 * DIM + col]     = v2;
                out[(size_t)r1 * DIM + col + 1] = v3;
            }
        }
    }
}

// ---------------- launcher ----------------
extern "C" void kernel_launch(void* const* d_in, const int* in_sizes, int n_in,
                              void* d_out, int out_size)
{
    const float* x    = (const float*)d_in[0];
    const float* wg   = (const float*)d_in[1];
    const float* w1   = (const float*)d_in[2];
    const float* w2   = (const float*)d_in[3];
    const float* w3   = (const float*)d_in[4];
    const float* wsg  = (const float*)d_in[5];
    const float* wsu  = (const float*)d_in[6];
    const float* wsd  = (const float*)d_in[7];
    float* out = (float*)d_out;

    const int smem_routed = (2 * 64 * XS_STRIDE + 2 * 64 * HS_STRIDE) * 4;  // 172032
    const int smem_shared = (2 * 64 * XS_STRIDE + 1 * 64 * HS_STRIDE) * 4;  // 104448
    const int smem_final  = (2 * 64 * XS_STRIDE) * 4;                        // 36864

    cudaFuncSetAttribute(routed_mma,  cudaFuncAttributeMaxDynamicSharedMemorySize, smem_routed);
    cudaFuncSetAttribute(shared1_mma, cudaFuncAttributeMaxDynamicSharedMemorySize, smem_shared);
    cudaFuncSetAttribute(final_mma,   cudaFuncAttributeMaxDynamicSharedMemorySize, smem_final);

    router_kernel<<<T_TOK, 64>>>(x, wg);
    group_kernel<<<NEXP, 1024>>>();
    routed_mma<<<dim3(T_TOK / 64, NEXP), 256, smem_routed>>>(x, w1, w2, w3);
    shared1_mma<<<dim3(T_TOK / 64, SINTER / 256), 256, smem_shared>>>(x, wsg, wsu);
    final_mma<<<T_TOK / 64, 256, smem_final>>>(wsd, out);
}

// round 3
// speedup vs baseline: 1.9588x; 1.8487x over previous
#include <cuda_runtime.h>
#include <math.h>
#include <stdint.h>

#define T_TOK   1024
#define DIM     512
#define INTER   256
#define SINTER  1024
#define NEXP    64
#define TOPK    6
#define KC      32
#define AST     36      // A smem stride (conflict-free for frag pattern)
#define BST     36      // B smem stride
#define HST     260     // h / [k][n] smem stride

// ---------------- scratch (device globals; no allocation) ----------------
__device__ int   g_topk_idx[T_TOK * TOPK];
__device__ float g_topk_w[T_TOK * TOPK];
__device__ int   g_counts[NEXP];
__device__ int   g_tok[NEXP * T_TOK];
__device__ int   g_tslot[NEXP * T_TOK];
__device__ float g_tw[NEXP * T_TOK];
__device__ float g_contrib[T_TOK * TOPK * DIM];   // 12.6 MB
__device__ float g_hs[T_TOK * SINTER];            // 4 MB
__device__ float g_part[4 * T_TOK * DIM];         // 8 MB split-K partials

// ---------------- helpers ----------------
__device__ __forceinline__ uint32_t f2tf32(float v) {
    uint32_t r; asm("cvt.rna.tf32.f32 %0, %1;" : "=r"(r) : "f"(v)); return r;
}
__device__ __forceinline__ void split(float v, uint32_t& hi, uint32_t& lo) {
    uint32_t h = f2tf32(v);
    hi = h;
    lo = __float_as_uint(v - __uint_as_float(h));
}
__device__ __forceinline__ void mma8(float c[4], const uint32_t a[4],
                                     uint32_t b0, uint32_t b1) {
    asm volatile(
        "mma.sync.aligned.m16n8k8.row.col.f32.tf32.tf32.f32 "
        "{%0,%1,%2,%3}, {%4,%5,%6,%7}, {%8,%9}, {%0,%1,%2,%3};"
        : "+f"(c[0]), "+f"(c[1]), "+f"(c[2]), "+f"(c[3])
        : "r"(a[0]), "r"(a[1]), "r"(a[2]), "r"(a[3]), "r"(b0), "r"(b1));
}
__device__ __forceinline__ void cp16(float* dst_smem, const float* src) {
    uint32_t d = (uint32_t)__cvta_generic_to_shared(dst_smem);
    asm volatile("cp.async.cg.shared.global [%0], [%1], 16;" :: "r"(d), "l"(src));
}
__device__ __forceinline__ void cpcommit() {
    asm volatile("cp.async.commit_group;" ::: "memory");
}
template <int N> __device__ __forceinline__ void cpwait() {
    asm volatile("cp.async.wait_group %0;" :: "n"(N) : "memory");
}

// 64x256xKC chunk of MMAs: A raw [64][AST], B raw [256][BST], split 3xTF32 at use.
__device__ __forceinline__ void gemm_chunk(const float* __restrict__ Asb,
                                           const float* __restrict__ Bsb,
                                           int wid, int gid, int l4,
                                           float c[4][4][4]) {
    #pragma unroll
    for (int ks = 0; ks < 4; ks++) {
        uint32_t ah[4][4], al[4][4];
        #pragma unroll
        for (int rt = 0; rt < 4; rt++) {
            int r0 = rt * 16 + gid;
            int cc = ks * 8 + l4;
            split(Asb[r0 * AST + cc],           ah[rt][0], al[rt][0]);
            split(Asb[(r0 + 8) * AST + cc],     ah[rt][1], al[rt][1]);
            split(Asb[r0 * AST + cc + 4],       ah[rt][2], al[rt][2]);
            split(Asb[(r0 + 8) * AST + cc + 4], ah[rt][3], al[rt][3]);
        }
        #pragma unroll
        for (int ct = 0; ct < 4; ct++) {
            int n = wid * 32 + ct * 8 + gid;
            uint32_t bh0, bl0, bh1, bl1;
            split(Bsb[n * BST + ks * 8 + l4],     bh0, bl0);
            split(Bsb[n * BST + ks * 8 + l4 + 4], bh1, bl1);
            #pragma unroll
            for (int rt = 0; rt < 4; rt++) {
                mma8(c[rt][ct], ah[rt], bh0, bh1);
                mma8(c[rt][ct], ah[rt], bl0, bl1);
                mma8(c[rt][ct], al[rt], bh0, bh1);
            }
        }
    }
}

// ---------------- 1. router: 16 tokens/block ----------------
__global__ __launch_bounds__(256) void router_kernel(
    const float* __restrict__ x, const float* __restrict__ wg)
{
    const int t0  = blockIdx.x * 16;
    const int tid = threadIdx.x;
    __shared__ float xs[16 * DIM];
    __shared__ float sc[16 * NEXP];

    for (int idx = tid; idx < 16 * DIM / 4; idx += 256)
        *(float4*)&xs[idx * 4] = *(const float4*)&x[(size_t)t0 * DIM + idx * 4];
    __syncthreads();

    int e  = tid & 63;
    int tg = tid >> 6;
    const float4* wr = (const float4*)(wg + (size_t)e * DIM);
    for (int tt = tg; tt < 16; tt += 4) {
        float acc = 0.f;
        #pragma unroll 4
        for (int d4 = 0; d4 < DIM / 4; d4++) {
            float4 w  = wr[d4];
            float4 xv = *(const float4*)&xs[tt * DIM + d4 * 4];
            acc = fmaf(w.x, xv.x, fmaf(w.y, xv.y, fmaf(w.z, xv.z, fmaf(w.w, xv.w, acc))));
        }
        sc[tt * NEXP + e] = acc;
    }
    __syncthreads();

    if (tid < 16) {
        float* s = &sc[tid * NEXP];
        float vals[TOPK]; int idx[TOPK];
        for (int k = 0; k < TOPK; k++) {
            float best = -INFINITY; int bi = 0;
            for (int ee = 0; ee < NEXP; ee++)
                if (s[ee] > best) { best = s[ee]; bi = ee; }
            vals[k] = best; idx[k] = bi; s[bi] = -INFINITY;
        }
        float mx = vals[0];
        float w6[TOPK]; float sum = 0.f;
        #pragma unroll
        for (int k = 0; k < TOPK; k++) { w6[k] = __expf(vals[k] - mx); sum += w6[k]; }
        float inv = 1.f / sum;
        int t = t0 + tid;
        #pragma unroll
        for (int k = 0; k < TOPK; k++) {
            g_topk_idx[t * TOPK + k] = idx[k];
            g_topk_w[t * TOPK + k]   = w6[k] * inv;
        }
    }
}

// ---------------- 2. deterministic grouping ----------------
__global__ __launch_bounds__(1024) void group_kernel()
{
    int e = blockIdx.x;
    int t = threadIdx.x;
    int slot = -1;
    #pragma unroll
    for (int k = 0; k < TOPK; k++)
        if (g_topk_idx[t * TOPK + k] == e) slot = k;
    int flag = (slot >= 0) ? 1 : 0;

    __shared__ int sc[T_TOK];
    sc[t] = flag;
    __syncthreads();
    for (int off = 1; off < T_TOK; off <<= 1) {
        int v = (t >= off) ? sc[t - off] : 0;
        __syncthreads();
        sc[t] += v;
        __syncthreads();
    }
    if (flag) {
        int pos = sc[t] - 1;
        g_tok[e * T_TOK + pos]   = t;
        g_tslot[e * T_TOK + pos] = slot;
        g_tw[e * T_TOK + pos]    = g_topk_w[t * TOPK + slot];
    }
    if (t == T_TOK - 1) g_counts[e] = sc[T_TOK - 1];
}

// ---------------- 3. fused routed experts + shared-expert up ----------------
// grid (16, NEXP+4). y<NEXP: expert block (up+silu+down -> contrib)
//                    y>=NEXP: shared col-tile (up+silu -> g_hs)
__global__ __launch_bounds__(256, 1) void ffn_mma(
    const float* __restrict__ x,
    const float* __restrict__ w1, const float* __restrict__ w2,
    const float* __restrict__ w3,
    const float* __restrict__ wsg, const float* __restrict__ wsu)
{
    extern __shared__ float sm[];
    float* As = sm;                                   // [2][64*AST]
    float* Bs = sm + 2 * 64 * AST;                    // [2][256*BST]
    float* Hs = sm + 2 * 64 * AST + 2 * 256 * BST;    // [64*HST]

    const int by = blockIdx.y;
    const bool is_shared = (by >= NEXP);
    const int tid  = threadIdx.x;
    const int wid  = tid >> 5;
    const int lane = tid & 31;
    const int gid  = lane >> 2;
    const int l4   = lane & 3;
    const int m0tok = blockIdx.x * 64;

    __shared__ int   s_row[64];
    __shared__ int   s_slot[64];
    __shared__ float s_w[64];

    int mr = 64, n0 = 0, e = 0;
    if (is_shared) {
        n0 = (by - NEXP) * 256;
        if (tid < 64) s_row[tid] = m0tok + tid;
    } else {
        e = by;
        int cnt = g_counts[e];
        if (m0tok >= cnt) return;
        mr = min(64, cnt - m0tok);
        if (tid < 64) {
            int mm = (tid < mr) ? tid : 0;
            s_row[tid]  = g_tok[e * T_TOK + m0tok + mm];
            s_slot[tid] = g_tslot[e * T_TOK + m0tok + mm];
            s_w[tid]    = g_tw[e * T_TOK + m0tok + mm];
        }
    }
    __syncthreads();

    // ======== phase A: gate (p=0) and up (p=1) projections ========
    for (int p = 0; p < 2; p++) {
        const float* Wb = is_shared
            ? ((p ? wsu : wsg) + (size_t)n0 * DIM)
            : ((p ? w3 : w1) + (size_t)e * INTER * DIM);

        float c[4][4][4];
        #pragma unroll
        for (int i = 0; i < 4; i++)
            #pragma unroll
            for (int j = 0; j < 4; j++)
                #pragma unroll
                for (int q = 0; q < 4; q++) c[i][j][q] = 0.f;

        // stage chunk 0 -> buf 0
        {
            #pragma unroll
            for (int j = 0; j < 2; j++) {
                int idx = tid + 256 * j;
                int row = idx >> 3, col = (idx & 7) * 4;
                cp16(&As[row * AST + col], x + (size_t)s_row[row] * DIM + col);
            }
            #pragma unroll
            for (int j = 0; j < 8; j++) {
                int idx = tid + 256 * j;
                int row = idx >> 3, col = (idx & 7) * 4;
                cp16(&Bs[row * BST + col], Wb + (size_t)row * DIM + col);
            }
            cpcommit();
        }
        for (int kc = 0; kc < DIM / KC; kc++) {
            int st = kc & 1;
            if (kc < DIM / KC - 1) {
                int kb = (kc + 1) * KC;
                int sn = st ^ 1;
                #pragma unroll
                for (int j = 0; j < 2; j++) {
                    int idx = tid + 256 * j;
                    int row = idx >> 3, col = (idx & 7) * 4;
                    cp16(&As[sn * 64 * AST + row * AST + col],
                         x + (size_t)s_row[row] * DIM + kb + col);
                }
                #pragma unroll
                for (int j = 0; j < 8; j++) {
                    int idx = tid + 256 * j;
                    int row = idx >> 3, col = (idx & 7) * 4;
                    cp16(&Bs[sn * 256 * BST + row * BST + col],
                         Wb + (size_t)row * DIM + kb + col);
                }
                cpcommit();
                cpwait<1>();
            } else {
                cpwait<0>();
            }
            __syncthreads();
            gemm_chunk(As + st * 64 * AST, Bs + st * 256 * BST, wid, gid, l4, c);
            __syncthreads();
        }

        // epilogue
        #pragma unroll
        for (int rt = 0; rt < 4; rt++) {
            #pragma unroll
            for (int ct = 0; ct < 4; ct++) {
                int col = wid * 32 + ct * 8 + 2 * l4;
                int r0 = rt * 16 + gid, r1 = r0 + 8;
                if (p == 0) {
                    Hs[r0 * HST + col]     = c[rt][ct][0];
                    Hs[r0 * HST + col + 1] = c[rt][ct][1];
                    Hs[r1 * HST + col]     = c[rt][ct][2];
                    Hs[r1 * HST + col + 1] = c[rt][ct][3];
                } else {
                    #pragma unroll
                    for (int q = 0; q < 4; q++) {
                        int rr  = (q < 2) ? r0 : r1;
                        int ccl = col + (q & 1);
                        float g = Hs[rr * HST + ccl];
                        float sv = (g / (1.f + __expf(-g))) * c[rt][ct][q];
                        if (is_shared)
                            g_hs[(size_t)(m0tok + rr) * SINTER + n0 + ccl] = sv;
                        else
                            Hs[rr * HST + ccl] = sv;
                    }
                }
            }
        }
    }
    if (is_shared) return;
    __syncthreads();   // Hs (h tile) visible to all warps

    // ======== phase B: y = h @ w2, N=512 in two 256-passes ========
    const float* W2e = w2 + (size_t)e * INTER * DIM;
    float* Bs2 = Bs;   // [32][HST] ([k][n] layout)

    for (int np = 0; np < 2; np++) {
        float c[4][4][4];
        #pragma unroll
        for (int i = 0; i < 4; i++)
            #pragma unroll
            for (int j = 0; j < 4; j++)
                #pragma unroll
                for (int q = 0; q < 4; q++) c[i][j][q] = 0.f;

        float4 pv[8];
        #pragma unroll
        for (int j = 0; j < 8; j++) {
            int idx = tid + 256 * j;
            int kl = idx >> 6, f4 = idx & 63;
            pv[j] = *(const float4*)(W2e + (size_t)kl * DIM + np * 256 + f4 * 4);
        }
        for (int kc = 0; kc < INTER / KC; kc++) {
            __syncthreads();
            #pragma unroll
            for (int j = 0; j < 8; j++) {
                int idx = tid + 256 * j;
                int kl = idx >> 6, f4 = idx & 63;
                *(float4*)&Bs2[kl * HST + f4 * 4] = pv[j];
            }
            __syncthreads();
            if (kc < INTER / KC - 1) {
                #pragma unroll
                for (int j = 0; j < 8; j++) {
                    int idx = tid + 256 * j;
                    int kl = idx >> 6, f4 = idx & 63;
                    pv[j] = *(const float4*)(W2e + (size_t)((kc + 1) * 32 + kl) * DIM
                                             + np * 256 + f4 * 4);
                }
            }
            #pragma unroll
            for (int ks = 0; ks < 4; ks++) {
                uint32_t ah[4][4], al[4][4];
                #pragma unroll
                for (int rt = 0; rt < 4; rt++) {
                    int r0 = rt * 16 + gid;
                    int cc = kc * 32 + ks * 8 + l4;
                    split(Hs[r0 * HST + cc],           ah[rt][0], al[rt][0]);
                    split(Hs[(r0 + 8) * HST + cc],     ah[rt][1], al[rt][1]);
                    split(Hs[r0 * HST + cc + 4],       ah[rt][2], al[rt][2]);
                    split(Hs[(r0 + 8) * HST + cc + 4], ah[rt][3], al[rt][3]);
                }
                #pragma unroll
                for (int ct = 0; ct < 4; ct++) {
                    int n = wid * 32 + ct * 8 + gid;
                    uint32_t bh0, bl0, bh1, bl1;
                    split(Bs2[(ks * 8 + l4) * HST + n],       bh0, bl0);
                    split(Bs2[(ks * 8 + l4 + 4) * HST + n],   bh1, bl1);
                    #pragma unroll
                    for (int rt = 0; rt < 4; rt++) {
                        mma8(c[rt][ct], ah[rt], bh0, bh1);
                        mma8(c[rt][ct], ah[rt], bl0, bl1);
                        mma8(c[rt][ct], al[rt], bh0, bh1);
                    }
                }
            }
        }
        // contrib epilogue
        #pragma unroll
        for (int rt = 0; rt < 4; rt++) {
            #pragma unroll
            for (int ct = 0; ct < 4; ct++) {
                int col = np * 256 + wid * 32 + ct * 8 + 2 * l4;
                int r0 = rt * 16 + gid, r1 = r0 + 8;
                if (r0 < mr) {
                    size_t base = ((size_t)(s_row[r0] * TOPK + s_slot[r0])) * DIM + col;
                    float w = s_w[r0];
                    *(float2*)&g_contrib[base] = make_float2(w * c[rt][ct][0], w * c[rt][ct][1]);
                }
                if (r1 < mr) {
                    size_t base = ((size_t)(s_row[r1] * TOPK + s_slot[r1])) * DIM + col;
                    float w = s_w[r1];
                    *(float2*)&g_contrib[base] = make_float2(w * c[rt][ct][2], w * c[rt][ct][3]);
                }
            }
        }
    }
}

// ---------------- 4. final GEMM split-K: part = H @ Wsd^T ----------------
// grid (16, 2, 4): m-tile, n-tile(256), k-split(256)
__global__ __launch_bounds__(256, 1) void final_mma(const float* __restrict__ wsd)
{
    extern __shared__ float sm[];
    float* As = sm;                    // [2][64*AST]
    float* Bs = sm + 2 * 64 * AST;     // [2][256*BST]

    const int m0 = blockIdx.x * 64;
    const int n0 = blockIdx.y * 256;
    const int k0 = blockIdx.z * 256;
    const int tid  = threadIdx.x;
    const int wid  = tid >> 5;
    const int lane = tid & 31;
    const int gid  = lane >> 2;
    const int l4   = lane & 3;

    float c[4][4][4];
    #pragma unroll
    for (int i = 0; i < 4; i++)
        #pragma unroll
        for (int j = 0; j < 4; j++)
            #pragma unroll
            for (int q = 0; q < 4; q++) c[i][j][q] = 0.f;

    {
        #pragma unroll
        for (int j = 0; j < 2; j++) {
            int idx = tid + 256 * j;
            int row = idx >> 3, col = (idx & 7) * 4;
            cp16(&As[row * AST + col], g_hs + (size_t)(m0 + row) * SINTER + k0 + col);
        }
        #pragma unroll
        for (int j = 0; j < 8; j++) {
            int idx = tid + 256 * j;
            int row = idx >> 3, col = (idx & 7) * 4;
            cp16(&Bs[row * BST + col], wsd + (size_t)(n0 + row) * SINTER + k0 + col);
        }
        cpcommit();
    }
    for (int kc = 0; kc < 256 / KC; kc++) {
        int st = kc & 1;
        if (kc < 256 / KC - 1) {
            int kb = (kc + 1) * KC;
            int sn = st ^ 1;
            #pragma unroll
            for (int j = 0; j < 2; j++) {
                int idx = tid + 256 * j;
                int row = idx >> 3, col = (idx & 7) * 4;
                cp16(&As[sn * 64 * AST + row * AST + col],
                     g_hs + (size_t)(m0 + row) * SINTER + k0 + kb + col);
            }
            #pragma unroll
            for (int j = 0; j < 8; j++) {
                int idx = tid + 256 * j;
                int row = idx >> 3, col = (idx & 7) * 4;
                cp16(&Bs[sn * 256 * BST + row * BST + col],
                     wsd + (size_t)(n0 + row) * SINTER + k0 + kb + col);
            }
            cpcommit();
            cpwait<1>();
        } else {
            cpwait<0>();
        }
        __syncthreads();
        gemm_chunk(As + st * 64 * AST, Bs + st * 256 * BST, wid, gid, l4, c);
        __syncthreads();
    }

    #pragma unroll
    for (int rt = 0; rt < 4; rt++) {
        #pragma unroll
        for (int ct = 0; ct < 4; ct++) {
            int col = n0 + wid * 32 + ct * 8 + 2 * l4;
            int r0 = m0 + rt * 16 + gid, r1 = r0 + 8;
            *(float2*)&g_part[((size_t)blockIdx.z * T_TOK + r0) * DIM + col]
                = make_float2(c[rt][ct][0], c[rt][ct][1]);
            *(float2*)&g_part[((size_t)blockIdx.z * T_TOK + r1) * DIM + col]
                = make_float2(c[rt][ct][2], c[rt][ct][3]);
        }
    }
}

// ---------------- 5. reduce: out = sum parts + sum contribs ----------------
__global__ __launch_bounds__(256) void reduce_kernel(float* __restrict__ out)
{
    int t = blockIdx.x;
    #pragma unroll
    for (int h = 0; h < 2; h++) {
        int d = threadIdx.x + h * 256;
        float v = 0.f;
        #pragma unroll
        for (int z = 0; z < 4; z++)
            v += g_part[((size_t)z * T_TOK + t) * DIM + d];
        #pragma unroll
        for (int k = 0; k < TOPK; k++)
            v += g_contrib[((size_t)t * TOPK + k) * DIM + d];
        out[(size_t)t * DIM + d] = v;
    }
}

// ---------------- launcher ----------------
extern "C" void kernel_launch(void* const* d_in, const int* in_sizes, int n_in,
                              void* d_out, int out_size)
{
    const float* x   = (const float*)d_in[0];
    const float* wg  = (const float*)d_in[1];
    const float* w1  = (const float*)d_in[2];
    const float* w2  = (const float*)d_in[3];
    const float* w3  = (const float*)d_in[4];
    const float* wsg = (const float*)d_in[5];
    const float* wsu = (const float*)d_in[6];
    const float* wsd = (const float*)d_in[7];
    float* out = (float*)d_out;

    const int smem_ffn   = (2 * 64 * AST + 2 * 256 * BST + 64 * HST) * 4;  // 158720
    const int smem_final = (2 * 64 * AST + 2 * 256 * BST) * 4;             // 92160

    cudaFuncSetAttribute(ffn_mma,   cudaFuncAttributeMaxDynamicSharedMemorySize, smem_ffn);
    cudaFuncSetAttribute(final_mma, cudaFuncAttributeMaxDynamicSharedMemorySize, smem_final);

    router_kernel<<<T_TOK / 16, 256>>>(x, wg);
    group_kernel<<<NEXP, 1024>>>();
    ffn_mma<<<dim3(16, NEXP + 4), 256, smem_ffn>>>(x, w1, w2, w3, wsg, wsu);
    final_mma<<<dim3(16, 2, 4), 256, smem_final>>>(wsd);
    reduce_kernel<<<T_TOK, 256>>>(out);
}

// round 4
// speedup vs baseline: 2.4214x; 1.2361x over previous
#include <cuda_runtime.h>
#include <math.h>
#include <stdint.h>

#define T_TOK   1024
#define DIM     512
#define INTER   256
#define SINTER  1024
#define NEXP    64
#define TOPK    6
#define KC      32
#define AST     36      // A smem stride (conflict-free)
#define BST     36      // B smem stride
#define HST     260     // h / [k][n] smem stride
#define KSPLIT  8

// ---------------- scratch (device globals; no allocation) ----------------
__device__ int   g_topk_idx[T_TOK * TOPK];
__device__ float g_topk_w[T_TOK * TOPK];
__device__ int   g_counts[NEXP];
__device__ int   g_tok[NEXP * T_TOK];
__device__ int   g_tslot[NEXP * T_TOK];
__device__ float g_tw[NEXP * T_TOK];
__device__ float g_contrib[T_TOK * TOPK * DIM];     // 12.6 MB
__device__ float g_hs[T_TOK * SINTER];              // 4 MB (tf32 bits)
__device__ float g_part[KSPLIT * T_TOK * DIM];      // 16 MB split-K partials

// ---------------- helpers ----------------
__device__ __forceinline__ uint32_t f2tf32(float v) {
    uint32_t r; asm("cvt.rna.tf32.f32 %0, %1;" : "=r"(r) : "f"(v)); return r;
}
__device__ __forceinline__ float tf32f(float v) {
    return __uint_as_float(f2tf32(v));
}
__device__ __forceinline__ void split(float v, uint32_t& hi, uint32_t& lo) {
    uint32_t h = f2tf32(v);
    hi = h;
    lo = __float_as_uint(v - __uint_as_float(h));
}
__device__ __forceinline__ void mma8(float c[4], const uint32_t a[4],
                                     uint32_t b0, uint32_t b1) {
    asm volatile(
        "mma.sync.aligned.m16n8k8.row.col.f32.tf32.tf32.f32 "
        "{%0,%1,%2,%3}, {%4,%5,%6,%7}, {%8,%9}, {%0,%1,%2,%3};"
        : "+f"(c[0]), "+f"(c[1]), "+f"(c[2]), "+f"(c[3])
        : "r"(a[0]), "r"(a[1]), "r"(a[2]), "r"(a[3]), "r"(b0), "r"(b1));
}
__device__ __forceinline__ void cp16(float* dst_smem, const float* src) {
    uint32_t d = (uint32_t)__cvta_generic_to_shared(dst_smem);
    asm volatile("cp.async.cg.shared.global [%0], [%1], 16;" :: "r"(d), "l"(src));
}
__device__ __forceinline__ void cpcommit() {
    asm volatile("cp.async.commit_group;" ::: "memory");
}
template <int N> __device__ __forceinline__ void cpwait() {
    asm volatile("cp.async.wait_group %0;" :: "n"(N) : "memory");
}

// 64x256xKC chunk, 2-term TF32, term-major ordering.
// A smem holds tf32 bits already; B smem holds raw fp32 (split at use).
__device__ __forceinline__ void gemm_chunk2(const float* __restrict__ Asb,
                                            const float* __restrict__ Bsb,
                                            int wid, int gid, int l4,
                                            float c[4][4][4]) {
    #pragma unroll
    for (int ks = 0; ks < 4; ks++) {
        uint32_t ah[4][4];
        #pragma unroll
        for (int rt = 0; rt < 4; rt++) {
            int r0 = rt * 16 + gid;
            int cc = ks * 8 + l4;
            ah[rt][0] = __float_as_uint(Asb[r0 * AST + cc]);
            ah[rt][1] = __float_as_uint(Asb[(r0 + 8) * AST + cc]);
            ah[rt][2] = __float_as_uint(Asb[r0 * AST + cc + 4]);
            ah[rt][3] = __float_as_uint(Asb[(r0 + 8) * AST + cc + 4]);
        }
        uint32_t bh[4][2], bl[4][2];
        #pragma unroll
        for (int ct = 0; ct < 4; ct++) {
            int n = wid * 32 + ct * 8 + gid;
            split(Bsb[n * BST + ks * 8 + l4],     bh[ct][0], bl[ct][0]);
            split(Bsb[n * BST + ks * 8 + l4 + 4], bh[ct][1], bl[ct][1]);
        }
        #pragma unroll
        for (int ct = 0; ct < 4; ct++)
            #pragma unroll
            for (int rt = 0; rt < 4; rt++)
                mma8(c[rt][ct], ah[rt], bh[ct][0], bh[ct][1]);
        #pragma unroll
        for (int ct = 0; ct < 4; ct++)
            #pragma unroll
            for (int rt = 0; rt < 4; rt++)
                mma8(c[rt][ct], ah[rt], bl[ct][0], bl[ct][1]);
    }
}

// ---------------- 1. router: 16 tokens/block ----------------
__global__ __launch_bounds__(256) void router_kernel(
    const float* __restrict__ x, const float* __restrict__ wg)
{
    const int t0  = blockIdx.x * 16;
    const int tid = threadIdx.x;
    __shared__ float xs[16 * DIM];
    __shared__ float sc[16 * NEXP];

    for (int idx = tid; idx < 16 * DIM / 4; idx += 256)
        *(float4*)&xs[idx * 4] = *(const float4*)&x[(size_t)t0 * DIM + idx * 4];
    __syncthreads();

    int e  = tid & 63;
    int tg = tid >> 6;
    const float4* wr = (const float4*)(wg + (size_t)e * DIM);
    for (int tt = tg; tt < 16; tt += 4) {
        float acc = 0.f;
        #pragma unroll 4
        for (int d4 = 0; d4 < DIM / 4; d4++) {
            float4 w  = wr[d4];
            float4 xv = *(const float4*)&xs[tt * DIM + d4 * 4];
            acc = fmaf(w.x, xv.x, fmaf(w.y, xv.y, fmaf(w.z, xv.z, fmaf(w.w, xv.w, acc))));
        }
        sc[tt * NEXP + e] = acc;
    }
    __syncthreads();

    if (tid < 16) {
        float* s = &sc[tid * NEXP];
        float vals[TOPK]; int idx[TOPK];
        for (int k = 0; k < TOPK; k++) {
            float best = -INFINITY; int bi = 0;
            for (int ee = 0; ee < NEXP; ee++)
                if (s[ee] > best) { best = s[ee]; bi = ee; }
            vals[k] = best; idx[k] = bi; s[bi] = -INFINITY;
        }
        float mx = vals[0];
        float w6[TOPK]; float sum = 0.f;
        #pragma unroll
        for (int k = 0; k < TOPK; k++) { w6[k] = __expf(vals[k] - mx); sum += w6[k]; }
        float inv = 1.f / sum;
        int t = t0 + tid;
        #pragma unroll
        for (int k = 0; k < TOPK; k++) {
            g_topk_idx[t * TOPK + k] = idx[k];
            g_topk_w[t * TOPK + k]   = w6[k] * inv;
        }
    }
}

// ---------------- 2. deterministic grouping ----------------
__global__ __launch_bounds__(1024) void group_kernel()
{
    int e = blockIdx.x;
    int t = threadIdx.x;
    int slot = -1;
    #pragma unroll
    for (int k = 0; k < TOPK; k++)
        if (g_topk_idx[t * TOPK + k] == e) slot = k;
    int flag = (slot >= 0) ? 1 : 0;

    __shared__ int sc[T_TOK];
    sc[t] = flag;
    __syncthreads();
    for (int off = 1; off < T_TOK; off <<= 1) {
        int v = (t >= off) ? sc[t - off] : 0;
        __syncthreads();
        sc[t] += v;
        __syncthreads();
    }
    if (flag) {
        int pos = sc[t] - 1;
        g_tok[e * T_TOK + pos]   = t;
        g_tslot[e * T_TOK + pos] = slot;
        g_tw[e * T_TOK + pos]    = g_topk_w[t * TOPK + slot];
    }
    if (t == T_TOK - 1) g_counts[e] = sc[T_TOK - 1];
}

// ---------------- 3. fused routed experts + shared-expert up ----------------
__global__ __launch_bounds__(256, 1) void ffn_mma(
    const float* __restrict__ x,
    const float* __restrict__ w1, const float* __restrict__ w2,
    const float* __restrict__ w3,
    const float* __restrict__ wsg, const float* __restrict__ wsu)
{
    extern __shared__ float sm[];
    float* As = sm;                                   // [2][64*AST] (tf32 bits)
    float* Bs = sm + 2 * 64 * AST;                    // [2][256*BST] raw
    float* Hs = sm + 2 * 64 * AST + 2 * 256 * BST;    // [64*HST]

    const int by = blockIdx.y;
    const bool is_shared = (by >= NEXP);
    const int tid  = threadIdx.x;
    const int wid  = tid >> 5;
    const int lane = tid & 31;
    const int gid  = lane >> 2;
    const int l4   = lane & 3;
    const int m0tok = blockIdx.x * 64;

    __shared__ int   s_row[64];
    __shared__ int   s_slot[64];
    __shared__ float s_w[64];

    int mr = 64, n0 = 0, e = 0;
    if (is_shared) {
        n0 = (by - NEXP) * 256;
        if (tid < 64) s_row[tid] = m0tok + tid;
    } else {
        e = by;
        int cnt = g_counts[e];
        if (m0tok >= cnt) return;
        mr = min(64, cnt - m0tok);
        if (tid < 64) {
            int mm = (tid < mr) ? tid : 0;
            s_row[tid]  = g_tok[e * T_TOK + m0tok + mm];
            s_slot[tid] = g_tslot[e * T_TOK + m0tok + mm];
            s_w[tid]    = g_tw[e * T_TOK + m0tok + mm];
        }
    }
    __syncthreads();

    const int ar = tid >> 2;            // A-stage row (0..63)
    const int ac = (tid & 3) * 8;       // A-stage col group

    // ======== phase A: gate (p=0) and up (p=1) projections ========
    for (int p = 0; p < 2; p++) {
        const float* Wb = is_shared
            ? ((p ? wsu : wsg) + (size_t)n0 * DIM)
            : ((p ? w3 : w1) + (size_t)e * INTER * DIM);
        const float* xrow = x + (size_t)s_row[ar] * DIM;

        float c[4][4][4];
        #pragma unroll
        for (int i = 0; i < 4; i++)
            #pragma unroll
            for (int j = 0; j < 4; j++)
                #pragma unroll
                for (int q = 0; q < 4; q++) c[i][j][q] = 0.f;

        // prefetch A chunk 0 into regs; B chunk 0 via cp.async
        float4 pa0 = *(const float4*)(xrow + ac);
        float4 pa1 = *(const float4*)(xrow + ac + 4);
        #pragma unroll
        for (int j = 0; j < 8; j++) {
            int idx = tid + 256 * j;
            int row = idx >> 3, col = (idx & 7) * 4;
            cp16(&Bs[row * BST + col], Wb + (size_t)row * DIM + col);
        }
        cpcommit();

        for (int kc = 0; kc < DIM / KC; kc++) {
            int st = kc & 1;
            // write A (tf32) for this chunk
            {
                float* ad = As + st * 64 * AST + ar * AST + ac;
                ad[0] = tf32f(pa0.x); ad[1] = tf32f(pa0.y);
                ad[2] = tf32f(pa0.z); ad[3] = tf32f(pa0.w);
                ad[4] = tf32f(pa1.x); ad[5] = tf32f(pa1.y);
                ad[6] = tf32f(pa1.z); ad[7] = tf32f(pa1.w);
            }
            if (kc < DIM / KC - 1) {
                int kb = (kc + 1) * KC;
                int sn = st ^ 1;
                pa0 = *(const float4*)(xrow + kb + ac);
                pa1 = *(const float4*)(xrow + kb + ac + 4);
                #pragma unroll
                for (int j = 0; j < 8; j++) {
                    int idx = tid + 256 * j;
                    int row = idx >> 3, col = (idx & 7) * 4;
                    cp16(&Bs[sn * 256 * BST + row * BST + col],
                         Wb + (size_t)row * DIM + kb + col);
                }
                cpcommit();
                cpwait<1>();
            } else {
                cpwait<0>();
            }
            __syncthreads();
            gemm_chunk2(As + st * 64 * AST, Bs + st * 256 * BST, wid, gid, l4, c);
            __syncthreads();
        }

        // epilogue
        #pragma unroll
        for (int rt = 0; rt < 4; rt++) {
            #pragma unroll
            for (int ct = 0; ct < 4; ct++) {
                int col = wid * 32 + ct * 8 + 2 * l4;
                int r0 = rt * 16 + gid, r1 = r0 + 8;
                if (p == 0) {
                    Hs[r0 * HST + col]     = c[rt][ct][0];
                    Hs[r0 * HST + col + 1] = c[rt][ct][1];
                    Hs[r1 * HST + col]     = c[rt][ct][2];
                    Hs[r1 * HST + col + 1] = c[rt][ct][3];
                } else {
                    #pragma unroll
                    for (int q = 0; q < 4; q++) {
                        int rr  = (q < 2) ? r0 : r1;
                        int ccl = col + (q & 1);
                        float g = Hs[rr * HST + ccl];
                        float sv = (g / (1.f + __expf(-g))) * c[rt][ct][q];
                        if (is_shared)
                            g_hs[(size_t)(m0tok + rr) * SINTER + n0 + ccl] = tf32f(sv);
                        else
                            Hs[rr * HST + ccl] = tf32f(sv);
                    }
                }
            }
        }
    }
    if (is_shared) return;
    __syncthreads();   // Hs (tf32 h tile) visible to all warps

    // ======== phase B: y = h @ w2, N=512 in two 256-passes ========
    const float* W2e = w2 + (size_t)e * INTER * DIM;
    float* Bs2 = Bs;   // [32][HST] raw [k][n]

    for (int np = 0; np < 2; np++) {
        float c[4][4][4];
        #pragma unroll
        for (int i = 0; i < 4; i++)
            #pragma unroll
            for (int j = 0; j < 4; j++)
                #pragma unroll
                for (int q = 0; q < 4; q++) c[i][j][q] = 0.f;

        float4 pv[8];
        #pragma unroll
        for (int j = 0; j < 8; j++) {
            int idx = tid + 256 * j;
            int kl = idx >> 6, f4 = idx & 63;
            pv[j] = *(const float4*)(W2e + (size_t)kl * DIM + np * 256 + f4 * 4);
        }
        for (int kc = 0; kc < INTER / KC; kc++) {
            __syncthreads();
            #pragma unroll
            for (int j = 0; j < 8; j++) {
                int idx = tid + 256 * j;
                int kl = idx >> 6, f4 = idx & 63;
                *(float4*)&Bs2[kl * HST + f4 * 4] = pv[j];
            }
            __syncthreads();
            if (kc < INTER / KC - 1) {
                #pragma unroll
                for (int j = 0; j < 8; j++) {
                    int idx = tid + 256 * j;
                    int kl = idx >> 6, f4 = idx & 63;
                    pv[j] = *(const float4*)(W2e + (size_t)((kc + 1) * 32 + kl) * DIM
                                             + np * 256 + f4 * 4);
                }
            }
            #pragma unroll
            for (int ks = 0; ks < 4; ks++) {
                uint32_t ah[4][4];
                #pragma unroll
                for (int rt = 0; rt < 4; rt++) {
                    int r0 = rt * 16 + gid;
                    int cc = kc * 32 + ks * 8 + l4;
                    ah[rt][0] = __float_as_uint(Hs[r0 * HST + cc]);
                    ah[rt][1] = __float_as_uint(Hs[(r0 + 8) * HST + cc]);
                    ah[rt][2] = __float_as_uint(Hs[r0 * HST + cc + 4]);
                    ah[rt][3] = __float_as_uint(Hs[(r0 + 8) * HST + cc + 4]);
                }
                uint32_t bh[4][2], bl[4][2];
                #pragma unroll
                for (int ct = 0; ct < 4; ct++) {
                    int n = wid * 32 + ct * 8 + gid;
                    split(Bs2[(ks * 8 + l4) * HST + n],     bh[ct][0], bl[ct][0]);
                    split(Bs2[(ks * 8 + l4 + 4) * HST + n], bh[ct][1], bl[ct][1]);
                }
                #pragma unroll
                for (int ct = 0; ct < 4; ct++)
                    #pragma unroll
                    for (int rt = 0; rt < 4; rt++)
                        mma8(c[rt][ct], ah[rt], bh[ct][0], bh[ct][1]);
                #pragma unroll
                for (int ct = 0; ct < 4; ct++)
                    #pragma unroll
                    for (int rt = 0; rt < 4; rt++)
                        mma8(c[rt][ct], ah[rt], bl[ct][0], bl[ct][1]);
            }
        }
        // contrib epilogue
        #pragma unroll
        for (int rt = 0; rt < 4; rt++) {
            #pragma unroll
            for (int ct = 0; ct < 4; ct++) {
                int col = np * 256 + wid * 32 + ct * 8 + 2 * l4;
                int r0 = rt * 16 + gid, r1 = r0 + 8;
                if (r0 < mr) {
                    size_t base = ((size_t)(s_row[r0] * TOPK + s_slot[r0])) * DIM + col;
                    float w = s_w[r0];
                    *(float2*)&g_contrib[base] = make_float2(w * c[rt][ct][0], w * c[rt][ct][1]);
                }
                if (r1 < mr) {
                    size_t base = ((size_t)(s_row[r1] * TOPK + s_slot[r1])) * DIM + col;
                    float w = s_w[r1];
                    *(float2*)&g_contrib[base] = make_float2(w * c[rt][ct][2], w * c[rt][ct][3]);
                }
            }
        }
    }
}

// ---------------- 4. final GEMM split-K(8): part = H @ Wsd^T ----------------
// grid (16, 2, 8): m-tile(64), n-tile(256), k-split(128)
__global__ __launch_bounds__(256, 2) void final_mma(const float* __restrict__ wsd)
{
    extern __shared__ float sm[];
    float* As = sm;                    // [2][64*AST] (tf32 bits from g_hs)
    float* Bs = sm + 2 * 64 * AST;     // [2][256*BST] raw

    const int m0 = blockIdx.x * 64;
    const int n0 = blockIdx.y * 256;
    const int k0 = blockIdx.z * 128;
    const int tid  = threadIdx.x;
    const int wid  = tid >> 5;
    const int lane = tid & 31;
    const int gid  = lane >> 2;
    const int l4   = lane & 3;

    float c[4][4][4];
    #pragma unroll
    for (int i = 0; i < 4; i++)
        #pragma unroll
        for (int j = 0; j < 4; j++)
            #pragma unroll
            for (int q = 0; q < 4; q++) c[i][j][q] = 0.f;

    {
        #pragma unroll
        for (int j = 0; j < 2; j++) {
            int idx = tid + 256 * j;
            int row = idx >> 3, col = (idx & 7) * 4;
            cp16(&As[row * AST + col], g_hs + (size_t)(m0 + row) * SINTER + k0 + col);
        }
        #pragma unroll
        for (int j = 0; j < 8; j++) {
            int idx = tid + 256 * j;
            int row = idx >> 3, col = (idx & 7) * 4;
            cp16(&Bs[row * BST + col], wsd + (size_t)(n0 + row) * SINTER + k0 + col);
        }
        cpcommit();
    }
    for (int kc = 0; kc < 128 / KC; kc++) {
        int st = kc & 1;
        if (kc < 128 / KC - 1) {
            int kb = (kc + 1) * KC;
            int sn = st ^ 1;
            #pragma unroll
            for (int j = 0; j < 2; j++) {
                int idx = tid + 256 * j;
                int row = idx >> 3, col = (idx & 7) * 4;
                cp16(&As[sn * 64 * AST + row * AST + col],
                     g_hs + (size_t)(m0 + row) * SINTER + k0 + kb + col);
            }
            #pragma unroll
            for (int j = 0; j < 8; j++) {
                int idx = tid + 256 * j;
                int row = idx >> 3, col = (idx & 7) * 4;
                cp16(&Bs[sn * 256 * BST + row * BST + col],
                     wsd + (size_t)(n0 + row) * SINTER + k0 + kb + col);
            }
            cpcommit();
            cpwait<1>();
        } else {
            cpwait<0>();
        }
        __syncthreads();
        gemm_chunk2(As + st * 64 * AST, Bs + st * 256 * BST, wid, gid, l4, c);
        __syncthreads();
    }

    #pragma unroll
    for (int rt = 0; rt < 4; rt++) {
        #pragma unroll
        for (int ct = 0; ct < 4; ct++) {
            int col = n0 + wid * 32 + ct * 8 + 2 * l4;
            int r0 = m0 + rt * 16 + gid, r1 = r0 + 8;
            *(float2*)&g_part[((size_t)blockIdx.z * T_TOK + r0) * DIM + col]
                = make_float2(c[rt][ct][0], c[rt][ct][1]);
            *(float2*)&g_part[((size_t)blockIdx.z * T_TOK + r1) * DIM + col]
                = make_float2(c[rt][ct][2], c[rt][ct][3]);
        }
    }
}

// ---------------- 5. reduce: out = sum parts + sum contribs ----------------
__global__ __launch_bounds__(256) void reduce_kernel(float* __restrict__ out)
{
    int t = blockIdx.x;
    #pragma unroll
    for (int h = 0; h < 2; h++) {
        int d = threadIdx.x + h * 256;
        float v = 0.f;
        #pragma unroll
        for (int z = 0; z < KSPLIT; z++)
            v += g_part[((size_t)z * T_TOK + t) * DIM + d];
        #pragma unroll
        for (int k = 0; k < TOPK; k++)
            v += g_contrib[((size_t)t * TOPK + k) * DIM + d];
        out[(size_t)t * DIM + d] = v;
    }
}

// ---------------- launcher ----------------
extern "C" void kernel_launch(void* const* d_in, const int* in_sizes, int n_in,
                              void* d_out, int out_size)
{
    const float* x   = (const float*)d_in[0];
    const float* wg  = (const float*)d_in[1];
    const float* w1  = (const float*)d_in[2];
    const float* w2  = (const float*)d_in[3];
    const float* w3  = (const float*)d_in[4];
    const float* wsg = (const float*)d_in[5];
    const float* wsu = (const float*)d_in[6];
    const float* wsd = (const float*)d_in[7];
    float* out = (float*)d_out;

    const int smem_ffn   = (2 * 64 * AST + 2 * 256 * BST + 64 * HST) * 4;  // 158720
    const int smem_final = (2 * 64 * AST + 2 * 256 * BST) * 4;             // 92160

    cudaFuncSetAttribute(ffn_mma,   cudaFuncAttributeMaxDynamicSharedMemorySize, smem_ffn);
    cudaFuncSetAttribute(final_mma, cudaFuncAttributeMaxDynamicSharedMemorySize, smem_final);

    router_kernel<<<T_TOK / 16, 256>>>(x, wg);
    group_kernel<<<NEXP, 1024>>>();
    ffn_mma<<<dim3(16, NEXP + 4), 256, smem_ffn>>>(x, w1, w2, w3, wsg, wsu);
    final_mma<<<dim3(16, 2, KSPLIT), 256, smem_final>>>(wsd);
    reduce_kernel<<<T_TOK, 256>>>(out);
}

// round 5
// speedup vs baseline: 2.4361x; 1.0061x over previous
#include <cuda_runtime.h>
#include <math.h>
#include <stdint.h>

#define T_TOK   1024
#define DIM     512
#define INTER   256
#define SINTER  1024
#define NEXP    64
#define TOPK    6
#define KC      32
#define AST     36      // A smem stride (conflict-free)
#define BST     36      // B smem stride ([n][k] tiles)
#define KNST    264     // [k][n] tile stride (264 mod 32 = 8 -> conflict-free)
#define KSPLIT  8

// ---------------- scratch (device globals; no allocation) ----------------
__device__ int   g_topk_idx[T_TOK * TOPK];
__device__ float g_topk_w[T_TOK * TOPK];
__device__ int   g_counts[NEXP];
__device__ int   g_tok[NEXP * T_TOK];
__device__ int   g_tslot[NEXP * T_TOK];
__device__ float g_tw[NEXP * T_TOK];
__device__ float g_contrib[T_TOK * TOPK * DIM];     // 12.6 MB
__device__ float g_hs[T_TOK * SINTER];              // 4 MB shared h (tf32 bits)
__device__ float g_part[KSPLIT * T_TOK * DIM];      // 16 MB split-K partials
__device__ float g_gate_e[NEXP * T_TOK * INTER];    // 64 MB raw expert gate
__device__ float g_he[NEXP * T_TOK * INTER];        // 64 MB expert h (tf32 bits)
__device__ float g_gate_s[T_TOK * SINTER];          // 4 MB raw shared gate

// ---------------- helpers ----------------
__device__ __forceinline__ uint32_t f2tf32(float v) {
    uint32_t r; asm("cvt.rna.tf32.f32 %0, %1;" : "=r"(r) : "f"(v)); return r;
}
__device__ __forceinline__ float tf32f(float v) {
    return __uint_as_float(f2tf32(v));
}
__device__ __forceinline__ void split(float v, uint32_t& hi, uint32_t& lo) {
    uint32_t h = f2tf32(v);
    hi = h;
    lo = __float_as_uint(v - __uint_as_float(h));
}
__device__ __forceinline__ void mma8(float c[4], const uint32_t a[4],
                                     uint32_t b0, uint32_t b1) {
    asm volatile(
        "mma.sync.aligned.m16n8k8.row.col.f32.tf32.tf32.f32 "
        "{%0,%1,%2,%3}, {%4,%5,%6,%7}, {%8,%9}, {%0,%1,%2,%3};"
        : "+f"(c[0]), "+f"(c[1]), "+f"(c[2]), "+f"(c[3])
        : "r"(a[0]), "r"(a[1]), "r"(a[2]), "r"(a[3]), "r"(b0), "r"(b1));
}
__device__ __forceinline__ void cp16(float* dst_smem, const float* src) {
    uint32_t d = (uint32_t)__cvta_generic_to_shared(dst_smem);
    asm volatile("cp.async.cg.shared.global [%0], [%1], 16;" :: "r"(d), "l"(src));
}
__device__ __forceinline__ void cpcommit() {
    asm volatile("cp.async.commit_group;" ::: "memory");
}
template <int N> __device__ __forceinline__ void cpwait() {
    asm volatile("cp.async.wait_group %0;" :: "n"(N) : "memory");
}

// 64x256xKC chunk, 2-term TF32, term-major. A smem = tf32 bits; B smem raw [n][k].
__device__ __forceinline__ void gemm_chunk2(const float* __restrict__ Asb,
                                            const float* __restrict__ Bsb,
                                            int wid, int gid, int l4,
                                            float c[4][4][4]) {
    #pragma unroll
    for (int ks = 0; ks < 4; ks++) {
        uint32_t ah[4][4];
        #pragma unroll
        for (int rt = 0; rt < 4; rt++) {
            int r0 = rt * 16 + gid;
            int cc = ks * 8 + l4;
            ah[rt][0] = __float_as_uint(Asb[r0 * AST + cc]);
            ah[rt][1] = __float_as_uint(Asb[(r0 + 8) * AST + cc]);
            ah[rt][2] = __float_as_uint(Asb[r0 * AST + cc + 4]);
            ah[rt][3] = __float_as_uint(Asb[(r0 + 8) * AST + cc + 4]);
        }
        uint32_t bh[4][2], bl[4][2];
        #pragma unroll
        for (int ct = 0; ct < 4; ct++) {
            int n = wid * 32 + ct * 8 + gid;
            split(Bsb[n * BST + ks * 8 + l4],     bh[ct][0], bl[ct][0]);
            split(Bsb[n * BST + ks * 8 + l4 + 4], bh[ct][1], bl[ct][1]);
        }
        #pragma unroll
        for (int ct = 0; ct < 4; ct++)
            #pragma unroll
            for (int rt = 0; rt < 4; rt++)
                mma8(c[rt][ct], ah[rt], bh[ct][0], bh[ct][1]);
        #pragma unroll
        for (int ct = 0; ct < 4; ct++)
            #pragma unroll
            for (int rt = 0; rt < 4; rt++)
                mma8(c[rt][ct], ah[rt], bl[ct][0], bl[ct][1]);
    }
}

// ---------------- 1. router: 16 tokens/block ----------------
__global__ __launch_bounds__(256) void router_kernel(
    const float* __restrict__ x, const float* __restrict__ wg)
{
    const int t0  = blockIdx.x * 16;
    const int tid = threadIdx.x;
    __shared__ float xs[16 * DIM];
    __shared__ float sc[16 * NEXP];

    for (int idx = tid; idx < 16 * DIM / 4; idx += 256)
        *(float4*)&xs[idx * 4] = *(const float4*)&x[(size_t)t0 * DIM + idx * 4];
    __syncthreads();

    int e  = tid & 63;
    int tg = tid >> 6;
    const float4* wr = (const float4*)(wg + (size_t)e * DIM);
    for (int tt = tg; tt < 16; tt += 4) {
        float acc = 0.f;
        #pragma unroll 4
        for (int d4 = 0; d4 < DIM / 4; d4++) {
            float4 w  = wr[d4];
            float4 xv = *(const float4*)&xs[tt * DIM + d4 * 4];
            acc = fmaf(w.x, xv.x, fmaf(w.y, xv.y, fmaf(w.z, xv.z, fmaf(w.w, xv.w, acc))));
        }
        sc[tt * NEXP + e] = acc;
    }
    __syncthreads();

    if (tid < 16) {
        float* s = &sc[tid * NEXP];
        float vals[TOPK]; int idx[TOPK];
        for (int k = 0; k < TOPK; k++) {
            float best = -INFINITY; int bi = 0;
            for (int ee = 0; ee < NEXP; ee++)
                if (s[ee] > best) { best = s[ee]; bi = ee; }
            vals[k] = best; idx[k] = bi; s[bi] = -INFINITY;
        }
        float mx = vals[0];
        float w6[TOPK]; float sum = 0.f;
        #pragma unroll
        for (int k = 0; k < TOPK; k++) { w6[k] = __expf(vals[k] - mx); sum += w6[k]; }
        float inv = 1.f / sum;
        int t = t0 + tid;
        #pragma unroll
        for (int k = 0; k < TOPK; k++) {
            g_topk_idx[t * TOPK + k] = idx[k];
            g_topk_w[t * TOPK + k]   = w6[k] * inv;
        }
    }
}

// ---------------- 2. deterministic grouping ----------------
__global__ __launch_bounds__(1024) void group_kernel()
{
    int e = blockIdx.x;
    int t = threadIdx.x;
    int slot = -1;
    #pragma unroll
    for (int k = 0; k < TOPK; k++)
        if (g_topk_idx[t * TOPK + k] == e) slot = k;
    int flag = (slot >= 0) ? 1 : 0;

    __shared__ int sc[T_TOK];
    sc[t] = flag;
    __syncthreads();
    for (int off = 1; off < T_TOK; off <<= 1) {
        int v = (t >= off) ? sc[t - off] : 0;
        __syncthreads();
        sc[t] += v;
        __syncthreads();
    }
    if (flag) {
        int pos = sc[t] - 1;
        g_tok[e * T_TOK + pos]   = t;
        g_tslot[e * T_TOK + pos] = slot;
        g_tw[e * T_TOK + pos]    = g_topk_w[t * TOPK + slot];
    }
    if (t == T_TOK - 1) g_counts[e] = sc[T_TOK - 1];
}

// ---------------- 3. up-projection (experts + shared), gate & up passes ----
// grid (16, NEXP+4). y<NEXP: expert; y>=NEXP: shared n-tile of 256.
__global__ __launch_bounds__(256, 2) void up_mma(
    const float* __restrict__ x,
    const float* __restrict__ w1, const float* __restrict__ w3,
    const float* __restrict__ wsg, const float* __restrict__ wsu)
{
    extern __shared__ float sm[];
    float* As = sm;                      // [2][64*AST] tf32 bits
    float* Bs = sm + 2 * 64 * AST;       // [2][256*BST] raw

    const int by = blockIdx.y;
    const bool is_shared = (by >= NEXP);
    const int tid  = threadIdx.x;
    const int wid  = tid >> 5;
    const int lane = tid & 31;
    const int gid  = lane >> 2;
    const int l4   = lane & 3;
    const int m0   = blockIdx.x * 64;

    __shared__ int s_row[64];

    int n0 = 0, e = 0;
    if (is_shared) {
        n0 = (by - NEXP) * 256;
        if (tid < 64) s_row[tid] = m0 + tid;
    } else {
        e = by;
        int cnt = g_counts[e];
        if (m0 >= cnt) return;
        int mr = min(64, cnt - m0);
        if (tid < 64) s_row[tid] = g_tok[e * T_TOK + m0 + ((tid < mr) ? tid : 0)];
    }
    __syncthreads();

    const int ar = tid >> 2;
    const int ac = (tid & 3) * 8;
    const float* xrow = x + (size_t)s_row[ar] * DIM;

    for (int p = 0; p < 2; p++) {
        const float* Wb = is_shared
            ? ((p ? wsu : wsg) + (size_t)n0 * DIM)
            : ((p ? w3 : w1) + (size_t)e * INTER * DIM);

        float c[4][4][4];
        #pragma unroll
        for (int i = 0; i < 4; i++)
            #pragma unroll
            for (int j = 0; j < 4; j++)
                #pragma unroll
                for (int q = 0; q < 4; q++) c[i][j][q] = 0.f;

        float4 pa0 = *(const float4*)(xrow + ac);
        float4 pa1 = *(const float4*)(xrow + ac + 4);
        #pragma unroll
        for (int j = 0; j < 8; j++) {
            int idx = tid + 256 * j;
            int row = idx >> 3, col = (idx & 7) * 4;
            cp16(&Bs[row * BST + col], Wb + (size_t)row * DIM + col);
        }
        cpcommit();

        for (int kc = 0; kc < DIM / KC; kc++) {
            int st = kc & 1;
            {
                float* ad = As + st * 64 * AST + ar * AST + ac;
                ad[0] = tf32f(pa0.x); ad[1] = tf32f(pa0.y);
                ad[2] = tf32f(pa0.z); ad[3] = tf32f(pa0.w);
                ad[4] = tf32f(pa1.x); ad[5] = tf32f(pa1.y);
                ad[6] = tf32f(pa1.z); ad[7] = tf32f(pa1.w);
            }
            if (kc < DIM / KC - 1) {
                int kb = (kc + 1) * KC;
                int sn = st ^ 1;
                pa0 = *(const float4*)(xrow + kb + ac);
                pa1 = *(const float4*)(xrow + kb + ac + 4);
                #pragma unroll
                for (int j = 0; j < 8; j++) {
                    int idx = tid + 256 * j;
                    int row = idx >> 3, col = (idx & 7) * 4;
                    cp16(&Bs[sn * 256 * BST + row * BST + col],
                         Wb + (size_t)row * DIM + kb + col);
                }
                cpcommit();
                cpwait<1>();
            } else {
                cpwait<0>();
            }
            __syncthreads();
            gemm_chunk2(As + st * 64 * AST, Bs + st * 256 * BST, wid, gid, l4, c);
            __syncthreads();
        }

        // epilogue: p=0 park raw gate; p=1 read gate (same thread), silu*up -> tf32 h
        #pragma unroll
        for (int rt = 0; rt < 4; rt++) {
            #pragma unroll
            for (int ct = 0; ct < 4; ct++) {
                int col = wid * 32 + ct * 8 + 2 * l4;
                #pragma unroll
                for (int half = 0; half < 2; half++) {
                    int r = rt * 16 + gid + half * 8;
                    float v0 = c[rt][ct][half * 2];
                    float v1 = c[rt][ct][half * 2 + 1];
                    size_t gidx = is_shared
                        ? (size_t)(m0 + r) * SINTER + n0 + col
                        : ((size_t)e * T_TOK + m0 + r) * INTER + col;
                    float* gateb = is_shared ? g_gate_s : g_gate_e;
                    float* hb    = is_shared ? g_hs     : g_he;
                    if (p == 0) {
                        *(float2*)&gateb[gidx] = make_float2(v0, v1);
                    } else {
                        float2 g = *(const float2*)&gateb[gidx];
                        float h0 = (g.x / (1.f + __expf(-g.x))) * v0;
                        float h1 = (g.y / (1.f + __expf(-g.y))) * v1;
                        *(float2*)&hb[gidx] = make_float2(tf32f(h0), tf32f(h1));
                    }
                }
            }
        }
    }
}

// ---------------- 4. expert down-projection: y = h @ w2^T(e) ----------------
// grid (16, NEXP, 2): m-tile(64), expert, n-half(256)
__global__ __launch_bounds__(256, 2) void down_mma(const float* __restrict__ w2)
{
    extern __shared__ float sm[];
    float* As = sm;                      // [2][64*AST] tf32 bits (h)
    float* Bs = sm + 2 * 64 * AST;       // [2][32*KNST] raw [k][n]

    const int e  = blockIdx.y;
    const int cnt = g_counts[e];
    const int m0 = blockIdx.x * 64;
    if (m0 >= cnt) return;
    const int mr = min(64, cnt - m0);
    const int n0 = blockIdx.z * 256;

    const int tid  = threadIdx.x;
    const int wid  = tid >> 5;
    const int lane = tid & 31;
    const int gid  = lane >> 2;
    const int l4   = lane & 3;

    __shared__ int   s_tok[64];
    __shared__ int   s_slot[64];
    __shared__ float s_w[64];
    if (tid < 64) {
        int mm = (tid < mr) ? tid : 0;
        s_tok[tid]  = g_tok[e * T_TOK + m0 + mm];
        s_slot[tid] = g_tslot[e * T_TOK + m0 + mm];
        s_w[tid]    = g_tw[e * T_TOK + m0 + mm];
    }

    const float* hbase  = g_he + ((size_t)e * T_TOK + m0) * INTER;
    const float* w2base = w2 + (size_t)e * INTER * DIM + n0;

    float c[4][4][4];
    #pragma unroll
    for (int i = 0; i < 4; i++)
        #pragma unroll
        for (int j = 0; j < 4; j++)
            #pragma unroll
            for (int q = 0; q < 4; q++) c[i][j][q] = 0.f;

    {
        #pragma unroll
        for (int j = 0; j < 2; j++) {
            int idx = tid + 256 * j;
            int row = idx >> 3, col = (idx & 7) * 4;
            cp16(&As[row * AST + col], hbase + (size_t)row * INTER + col);
        }
        #pragma unroll
        for (int j = 0; j < 8; j++) {
            int idx = tid + 256 * j;
            int kr = idx >> 6, nc = (idx & 63) * 4;
            cp16(&Bs[kr * KNST + nc], w2base + (size_t)kr * DIM + nc);
        }
        cpcommit();
    }
    for (int kc = 0; kc < INTER / KC; kc++) {
        int st = kc & 1;
        if (kc < INTER / KC - 1) {
            int kb = (kc + 1) * KC;
            int sn = st ^ 1;
            #pragma unroll
            for (int j = 0; j < 2; j++) {
                int idx = tid + 256 * j;
                int row = idx >> 3, col = (idx & 7) * 4;
                cp16(&As[sn * 64 * AST + row * AST + col],
                     hbase + (size_t)row * INTER + kb + col);
            }
            #pragma unroll
            for (int j = 0; j < 8; j++) {
                int idx = tid + 256 * j;
                int kr = idx >> 6, nc = (idx & 63) * 4;
                cp16(&Bs[sn * 32 * KNST + kr * KNST + nc],
                     w2base + (size_t)(kb + kr) * DIM + nc);
            }
            cpcommit();
            cpwait<1>();
        } else {
            cpwait<0>();
        }
        __syncthreads();
        const float* Asb = As + st * 64 * AST;
        const float* Bsb = Bs + st * 32 * KNST;
        #pragma unroll
        for (int ks = 0; ks < 4; ks++) {
            uint32_t ah[4][4];
            #pragma unroll
            for (int rt = 0; rt < 4; rt++) {
                int r0 = rt * 16 + gid;
                int cc = ks * 8 + l4;
                ah[rt][0] = __float_as_uint(Asb[r0 * AST + cc]);
                ah[rt][1] = __float_as_uint(Asb[(r0 + 8) * AST + cc]);
                ah[rt][2] = __float_as_uint(Asb[r0 * AST + cc + 4]);
                ah[rt][3] = __float_as_uint(Asb[(r0 + 8) * AST + cc + 4]);
            }
            uint32_t bh[4][2], bl[4][2];
            #pragma unroll
            for (int ct = 0; ct < 4; ct++) {
                int n = wid * 32 + ct * 8 + gid;
                split(Bsb[(ks * 8 + l4) * KNST + n],     bh[ct][0], bl[ct][0]);
                split(Bsb[(ks * 8 + l4 + 4) * KNST + n], bh[ct][1], bl[ct][1]);
            }
            #pragma unroll
            for (int ct = 0; ct < 4; ct++)
                #pragma unroll
                for (int rt = 0; rt < 4; rt++)
                    mma8(c[rt][ct], ah[rt], bh[ct][0], bh[ct][1]);
            #pragma unroll
            for (int ct = 0; ct < 4; ct++)
                #pragma unroll
                for (int rt = 0; rt < 4; rt++)
                    mma8(c[rt][ct], ah[rt], bl[ct][0], bl[ct][1]);
        }
        __syncthreads();
    }

    #pragma unroll
    for (int rt = 0; rt < 4; rt++) {
        #pragma unroll
        for (int ct = 0; ct < 4; ct++) {
            int col = n0 + wid * 32 + ct * 8 + 2 * l4;
            #pragma unroll
            for (int half = 0; half < 2; half++) {
                int r = rt * 16 + gid + half * 8;
                if (r < mr) {
                    size_t base = ((size_t)(s_tok[r] * TOPK + s_slot[r])) * DIM + col;
                    float w = s_w[r];
                    *(float2*)&g_contrib[base] =
                        make_float2(w * c[rt][ct][half * 2], w * c[rt][ct][half * 2 + 1]);
                }
            }
        }
    }
}

// ---------------- 5. final GEMM split-K(8): part = H @ Wsd^T ----------------
__global__ __launch_bounds__(256, 2) void final_mma(const float* __restrict__ wsd)
{
    extern __shared__ float sm[];
    float* As = sm;                    // [2][64*AST] tf32 bits
    float* Bs = sm + 2 * 64 * AST;     // [2][256*BST] raw

    const int m0 = blockIdx.x * 64;
    const int n0 = blockIdx.y * 256;
    const int k0 = blockIdx.z * 128;
    const int tid  = threadIdx.x;
    const int wid  = tid >> 5;
    const int lane = tid & 31;
    const int gid  = lane >> 2;
    const int l4   = lane & 3;

    float c[4][4][4];
    #pragma unroll
    for (int i = 0; i < 4; i++)
        #pragma unroll
        for (int j = 0; j < 4; j++)
            #pragma unroll
            for (int q = 0; q < 4; q++) c[i][j][q] = 0.f;

    {
        #pragma unroll
        for (int j = 0; j < 2; j++) {
            int idx = tid + 256 * j;
            int row = idx >> 3, col = (idx & 7) * 4;
            cp16(&As[row * AST + col], g_hs + (size_t)(m0 + row) * SINTER + k0 + col);
        }
        #pragma unroll
        for (int j = 0; j < 8; j++) {
            int idx = tid + 256 * j;
            int row = idx >> 3, col = (idx & 7) * 4;
            cp16(&Bs[row * BST + col], wsd + (size_t)(n0 + row) * SINTER + k0 + col);
        }
        cpcommit();
    }
    for (int kc = 0; kc < 128 / KC; kc++) {
        int st = kc & 1;
        if (kc < 128 / KC - 1) {
            int kb = (kc + 1) * KC;
            int sn = st ^ 1;
            #pragma unroll
            for (int j = 0; j < 2; j++) {
                int idx = tid + 256 * j;
                int row = idx >> 3, col = (idx & 7) * 4;
                cp16(&As[sn * 64 * AST + row * AST + col],
                     g_hs + (size_t)(m0 + row) * SINTER + k0 + kb + col);
            }
            #pragma unroll
            for (int j = 0; j < 8; j++) {
                int idx = tid + 256 * j;
                int row = idx >> 3, col = (idx & 7) * 4;
                cp16(&Bs[sn * 256 * BST + row * BST + col],
                     wsd + (size_t)(n0 + row) * SINTER + k0 + kb + col);
            }
            cpcommit();
            cpwait<1>();
        } else {
            cpwait<0>();
        }
        __syncthreads();
        gemm_chunk2(As + st * 64 * AST, Bs + st * 256 * BST, wid, gid, l4, c);
        __syncthreads();
    }

    #pragma unroll
    for (int rt = 0; rt < 4; rt++) {
        #pragma unroll
        for (int ct = 0; ct < 4; ct++) {
            int col = n0 + wid * 32 + ct * 8 + 2 * l4;
            int r0 = m0 + rt * 16 + gid, r1 = r0 + 8;
            *(float2*)&g_part[((size_t)blockIdx.z * T_TOK + r0) * DIM + col]
                = make_float2(c[rt][ct][0], c[rt][ct][1]);
            *(float2*)&g_part[((size_t)blockIdx.z * T_TOK + r1) * DIM + col]
                = make_float2(c[rt][ct][2], c[rt][ct][3]);
        }
    }
}

// ---------------- 6. reduce: out = sum parts + sum contribs ----------------
__global__ __launch_bounds__(256) void reduce_kernel(float* __restrict__ out)
{
    int t = blockIdx.x;
    #pragma unroll
    for (int h = 0; h < 2; h++) {
        int d = threadIdx.x + h * 256;
        float v = 0.f;
        #pragma unroll
        for (int z = 0; z < KSPLIT; z++)
            v += g_part[((size_t)z * T_TOK + t) * DIM + d];
        #pragma unroll
        for (int k = 0; k < TOPK; k++)
            v += g_contrib[((size_t)t * TOPK + k) * DIM + d];
        out[(size_t)t * DIM + d] = v;
    }
}

// ---------------- launcher ----------------
extern "C" void kernel_launch(void* const* d_in, const int* in_sizes, int n_in,
                              void* d_out, int out_size)
{
    const float* x   = (const float*)d_in[0];
    const float* wg  = (const float*)d_in[1];
    const float* w1  = (const float*)d_in[2];
    const float* w2  = (const float*)d_in[3];
    const float* w3  = (const float*)d_in[4];
    const float* wsg = (const float*)d_in[5];
    const float* wsu = (const float*)d_in[6];
    const float* wsd = (const float*)d_in[7];
    float* out = (float*)d_out;

    const int smem_up    = (2 * 64 * AST + 2 * 256 * BST) * 4;   // 92160
    const int smem_down  = (2 * 64 * AST + 2 * 32 * KNST) * 4;   // 86016
    const int smem_final = (2 * 64 * AST + 2 * 256 * BST) * 4;   // 92160

    cudaFuncSetAttribute(up_mma,    cudaFuncAttributeMaxDynamicSharedMemorySize, smem_up);
    cudaFuncSetAttribute(down_mma,  cudaFuncAttributeMaxDynamicSharedMemorySize, smem_down);
    cudaFuncSetAttribute(final_mma, cudaFuncAttributeMaxDynamicSharedMemorySize, smem_final);

    router_kernel<<<T_TOK / 16, 256>>>(x, wg);
    group_kernel<<<NEXP, 1024>>>();
    up_mma<<<dim3(16, NEXP + 4), 256, smem_up>>>(x, w1, w3, wsg, wsu);
    down_mma<<<dim3(16, NEXP, 2), 256, smem_down>>>(w2);
    final_mma<<<dim3(16, 2, KSPLIT), 256, smem_final>>>(wsd);
    reduce_kernel<<<T_TOK, 256>>>(out);
}

// round 6
// speedup vs baseline: 2.7709x; 1.1374x over previous
#include <cuda_runtime.h>
#include <math.h>
#include <stdint.h>

#define T_TOK   1024
#define DIM     512
#define INTER   256
#define SINTER  1024
#define NEXP    64
#define TOPK    6
#define KC      32
#define AST     36      // A smem stride (conflict-free)
#define BST     36      // B smem stride ([n][k] tiles)
#define KNST    264     // [k][n] tile stride
#define KSPLIT  8

// ---------------- scratch (device globals; no allocation) ----------------
__device__ int   g_topk_idx[T_TOK * TOPK];
__device__ float g_topk_w[T_TOK * TOPK];
__device__ int   g_counts[NEXP];
__device__ int   g_tok[NEXP * T_TOK];
__device__ int   g_tslot[NEXP * T_TOK];
__device__ float g_tw[NEXP * T_TOK];
__device__ float g_contrib[T_TOK * TOPK * DIM];     // 12.6 MB
__device__ float g_hs[T_TOK * SINTER];              // 4 MB shared h (tf32 bits)
__device__ float g_part[KSPLIT * T_TOK * DIM];      // 16 MB split-K partials
__device__ float g_he[NEXP * T_TOK * INTER];        // expert h (tf32 bits)

// ---------------- helpers ----------------
__device__ __forceinline__ uint32_t f2tf32(float v) {
    uint32_t r; asm("cvt.rna.tf32.f32 %0, %1;" : "=r"(r) : "f"(v)); return r;
}
__device__ __forceinline__ float tf32f(float v) {
    return __uint_as_float(f2tf32(v));
}
__device__ __forceinline__ void split(float v, uint32_t& hi, uint32_t& lo) {
    uint32_t h = f2tf32(v);
    hi = h;
    lo = __float_as_uint(v - __uint_as_float(h));
}
__device__ __forceinline__ void mma8(float c[4], const uint32_t a[4],
                                     uint32_t b0, uint32_t b1) {
    asm volatile(
        "mma.sync.aligned.m16n8k8.row.col.f32.tf32.tf32.f32 "
        "{%0,%1,%2,%3}, {%4,%5,%6,%7}, {%8,%9}, {%0,%1,%2,%3};"
        : "+f"(c[0]), "+f"(c[1]), "+f"(c[2]), "+f"(c[3])
        : "r"(a[0]), "r"(a[1]), "r"(a[2]), "r"(a[3]), "r"(b0), "r"(b1));
}
__device__ __forceinline__ void cp16(float* dst_smem, const float* src) {
    uint32_t d = (uint32_t)__cvta_generic_to_shared(dst_smem);
    asm volatile("cp.async.cg.shared.global [%0], [%1], 16;" :: "r"(d), "l"(src));
}
__device__ __forceinline__ void cpcommit() {
    asm volatile("cp.async.commit_group;" ::: "memory");
}
template <int N> __device__ __forceinline__ void cpwait() {
    asm volatile("cp.async.wait_group %0;" :: "n"(N) : "memory");
}

// 64x256xKC chunk, 2-term TF32, term-major. A smem = tf32 bits; B raw [n][k].
__device__ __forceinline__ void gemm_chunk2(const float* __restrict__ Asb,
                                            const float* __restrict__ Bsb,
                                            int wid, int gid, int l4,
                                            float c[4][4][4]) {
    #pragma unroll
    for (int ks = 0; ks < 4; ks++) {
        uint32_t ah[4][4];
        #pragma unroll
        for (int rt = 0; rt < 4; rt++) {
            int r0 = rt * 16 + gid;
            int cc = ks * 8 + l4;
            ah[rt][0] = __float_as_uint(Asb[r0 * AST + cc]);
            ah[rt][1] = __float_as_uint(Asb[(r0 + 8) * AST + cc]);
            ah[rt][2] = __float_as_uint(Asb[r0 * AST + cc + 4]);
            ah[rt][3] = __float_as_uint(Asb[(r0 + 8) * AST + cc + 4]);
        }
        uint32_t bh[4][2], bl[4][2];
        #pragma unroll
        for (int ct = 0; ct < 4; ct++) {
            int n = wid * 32 + ct * 8 + gid;
            split(Bsb[n * BST + ks * 8 + l4],     bh[ct][0], bl[ct][0]);
            split(Bsb[n * BST + ks * 8 + l4 + 4], bh[ct][1], bl[ct][1]);
        }
        #pragma unroll
        for (int ct = 0; ct < 4; ct++)
            #pragma unroll
            for (int rt = 0; rt < 4; rt++)
                mma8(c[rt][ct], ah[rt], bh[ct][0], bh[ct][1]);
        #pragma unroll
        for (int ct = 0; ct < 4; ct++)
            #pragma unroll
            for (int rt = 0; rt < 4; rt++)
                mma8(c[rt][ct], ah[rt], bl[ct][0], bl[ct][1]);
    }
}

// Same, but ct 0..1 -> B rows [wid*16 + ct*8], ct 2..3 -> B rows [128 + wid*16 + (ct-2)*8]
__device__ __forceinline__ void gemm_chunk_dual(const float* __restrict__ Asb,
                                                const float* __restrict__ Bsb,
                                                int wid, int gid, int l4,
                                                float c[4][4][4]) {
    #pragma unroll
    for (int ks = 0; ks < 4; ks++) {
        uint32_t ah[4][4];
        #pragma unroll
        for (int rt = 0; rt < 4; rt++) {
            int r0 = rt * 16 + gid;
            int cc = ks * 8 + l4;
            ah[rt][0] = __float_as_uint(Asb[r0 * AST + cc]);
            ah[rt][1] = __float_as_uint(Asb[(r0 + 8) * AST + cc]);
            ah[rt][2] = __float_as_uint(Asb[r0 * AST + cc + 4]);
            ah[rt][3] = __float_as_uint(Asb[(r0 + 8) * AST + cc + 4]);
        }
        uint32_t bh[4][2], bl[4][2];
        #pragma unroll
        for (int ct = 0; ct < 4; ct++) {
            int n = (ct < 2) ? (wid * 16 + ct * 8 + gid)
                             : (128 + wid * 16 + (ct - 2) * 8 + gid);
            split(Bsb[n * BST + ks * 8 + l4],     bh[ct][0], bl[ct][0]);
            split(Bsb[n * BST + ks * 8 + l4 + 4], bh[ct][1], bl[ct][1]);
        }
        #pragma unroll
        for (int ct = 0; ct < 4; ct++)
            #pragma unroll
            for (int rt = 0; rt < 4; rt++)
                mma8(c[rt][ct], ah[rt], bh[ct][0], bh[ct][1]);
        #pragma unroll
        for (int ct = 0; ct < 4; ct++)
            #pragma unroll
            for (int rt = 0; rt < 4; rt++)
                mma8(c[rt][ct], ah[rt], bl[ct][0], bl[ct][1]);
    }
}

// ---------------- 1. router ----------------
__global__ __launch_bounds__(256) void router_kernel(
    const float* __restrict__ x, const float* __restrict__ wg)
{
    const int t0  = blockIdx.x * 16;
    const int tid = threadIdx.x;
    __shared__ float xs[16 * DIM];
    __shared__ float sc[16 * NEXP];

    for (int idx = tid; idx < 16 * DIM / 4; idx += 256)
        *(float4*)&xs[idx * 4] = *(const float4*)&x[(size_t)t0 * DIM + idx * 4];
    __syncthreads();

    int e  = tid & 63;
    int tg = tid >> 6;
    const float4* wr = (const float4*)(wg + (size_t)e * DIM);
    for (int tt = tg; tt < 16; tt += 4) {
        float acc = 0.f;
        #pragma unroll 4
        for (int d4 = 0; d4 < DIM / 4; d4++) {
            float4 w  = wr[d4];
            float4 xv = *(const float4*)&xs[tt * DIM + d4 * 4];
            acc = fmaf(w.x, xv.x, fmaf(w.y, xv.y, fmaf(w.z, xv.z, fmaf(w.w, xv.w, acc))));
        }
        sc[tt * NEXP + e] = acc;
    }
    __syncthreads();

    if (tid < 16) {
        float* s = &sc[tid * NEXP];
        float vals[TOPK]; int idx[TOPK];
        for (int k = 0; k < TOPK; k++) {
            float best = -INFINITY; int bi = 0;
            for (int ee = 0; ee < NEXP; ee++)
                if (s[ee] > best) { best = s[ee]; bi = ee; }
            vals[k] = best; idx[k] = bi; s[bi] = -INFINITY;
        }
        float mx = vals[0];
        float w6[TOPK]; float sum = 0.f;
        #pragma unroll
        for (int k = 0; k < TOPK; k++) { w6[k] = __expf(vals[k] - mx); sum += w6[k]; }
        float inv = 1.f / sum;
        int t = t0 + tid;
        #pragma unroll
        for (int k = 0; k < TOPK; k++) {
            g_topk_idx[t * TOPK + k] = idx[k];
            g_topk_w[t * TOPK + k]   = w6[k] * inv;
        }
    }
}

// ---------------- 2. deterministic grouping ----------------
__global__ __launch_bounds__(1024) void group_kernel()
{
    int e = blockIdx.x;
    int t = threadIdx.x;
    int slot = -1;
    #pragma unroll
    for (int k = 0; k < TOPK; k++)
        if (g_topk_idx[t * TOPK + k] == e) slot = k;
    int flag = (slot >= 0) ? 1 : 0;

    __shared__ int sc[T_TOK];
    sc[t] = flag;
    __syncthreads();
    for (int off = 1; off < T_TOK; off <<= 1) {
        int v = (t >= off) ? sc[t - off] : 0;
        __syncthreads();
        sc[t] += v;
        __syncthreads();
    }
    if (flag) {
        int pos = sc[t] - 1;
        g_tok[e * T_TOK + pos]   = t;
        g_tslot[e * T_TOK + pos] = slot;
        g_tw[e * T_TOK + pos]    = g_topk_w[t * TOPK + slot];
    }
    if (t == T_TOK - 1) g_counts[e] = sc[T_TOK - 1];
}

// ---------------- 3. fused gate+up projection (experts + shared) ----------
// grid (16, NEXP*2 + SINTER/128).
//   by < NEXP*2:  e = by>>1, j = by&1 -> cols [j*128, j*128+128) of w1 AND w3
//   by >= NEXP*2: shared tile js -> cols [js*128, ...) of wsg AND wsu
__global__ __launch_bounds__(256, 2) void up_mma(
    const float* __restrict__ x,
    const float* __restrict__ w1, const float* __restrict__ w3,
    const float* __restrict__ wsg, const float* __restrict__ wsu)
{
    extern __shared__ float sm[];
    float* As = sm;                      // [2][64*AST] tf32 bits
    float* Bs = sm + 2 * 64 * AST;       // [2][256*BST]: rows 0..127 gate W, 128..255 up W

    const int by = blockIdx.y;
    const bool is_shared = (by >= NEXP * 2);
    const int tid  = threadIdx.x;
    const int wid  = tid >> 5;
    const int lane = tid & 31;
    const int gid  = lane >> 2;
    const int l4   = lane & 3;
    const int m0   = blockIdx.x * 64;

    __shared__ int s_row[64];

    const float *Wg, *Wu;
    int e = 0, ncol0 = 0;
    if (is_shared) {
        int js = by - NEXP * 2;
        ncol0 = js * 128;
        Wg = wsg + (size_t)ncol0 * DIM;
        Wu = wsu + (size_t)ncol0 * DIM;
        if (tid < 64) s_row[tid] = m0 + tid;
    } else {
        e = by >> 1;
        int cnt = g_counts[e];
        if (m0 >= cnt) return;
        int mr = min(64, cnt - m0);
        int j  = by & 1;
        ncol0 = j * 128;
        Wg = w1 + (size_t)e * INTER * DIM + (size_t)ncol0 * DIM;
        Wu = w3 + (size_t)e * INTER * DIM + (size_t)ncol0 * DIM;
        if (tid < 64) s_row[tid] = g_tok[e * T_TOK + m0 + ((tid < mr) ? tid : 0)];
    }
    __syncthreads();

    const int ar = tid >> 2;
    const int ac = (tid & 3) * 8;
    const float* xrow = x + (size_t)s_row[ar] * DIM;

    float c[4][4][4];   // ct 0..1 = gate, ct 2..3 = up
    #pragma unroll
    for (int i = 0; i < 4; i++)
        #pragma unroll
        for (int j = 0; j < 4; j++)
            #pragma unroll
            for (int q = 0; q < 4; q++) c[i][j][q] = 0.f;

    // preload chunk 0: A into regs, B via cp.async
    float4 pa0 = *(const float4*)(xrow + ac);
    float4 pa1 = *(const float4*)(xrow + ac + 4);
    #pragma unroll
    for (int j = 0; j < 8; j++) {
        int idx = tid + 256 * j;
        int row = idx >> 3, col = (idx & 7) * 4;
        const float* src = (row < 128) ? (Wg + (size_t)row * DIM + col)
                                       : (Wu + (size_t)(row - 128) * DIM + col);
        cp16(&Bs[row * BST + col], src);
    }
    cpcommit();

    const int NCH = DIM / KC;
    for (int kc = 0; kc < NCH; kc++) {
        int st = kc & 1;
        {   // stage A chunk kc as tf32 (buf st free: readers synced at kc-1)
            float* ad = As + st * 64 * AST + ar * AST + ac;
            ad[0] = tf32f(pa0.x); ad[1] = tf32f(pa0.y);
            ad[2] = tf32f(pa0.z); ad[3] = tf32f(pa0.w);
            ad[4] = tf32f(pa1.x); ad[5] = tf32f(pa1.y);
            ad[6] = tf32f(pa1.z); ad[7] = tf32f(pa1.w);
        }
        cpwait<0>();
        __syncthreads();   // B chunk kc visible; all warps past gemm kc-1
        if (kc < NCH - 1) {
            int kb = (kc + 1) * KC;
            int sn = st ^ 1;
            pa0 = *(const float4*)(xrow + kb + ac);
            pa1 = *(const float4*)(xrow + kb + ac + 4);
            #pragma unroll
            for (int j = 0; j < 8; j++) {
                int idx = tid + 256 * j;
                int row = idx >> 3, col = (idx & 7) * 4;
                const float* src = (row < 128) ? (Wg + (size_t)row * DIM + kb + col)
                                               : (Wu + (size_t)(row - 128) * DIM + kb + col);
                cp16(&Bs[sn * 256 * BST + row * BST + col], src);
            }
            cpcommit();
        }
        gemm_chunk_dual(As + st * 64 * AST, Bs + st * 256 * BST, wid, gid, l4, c);
    }

    // epilogue: h = silu(gate) * up, in registers -> tf32 -> global
    #pragma unroll
    for (int rt = 0; rt < 4; rt++) {
        #pragma unroll
        for (int ct = 0; ct < 2; ct++) {
            int col = ncol0 + wid * 16 + ct * 8 + 2 * l4;
            #pragma unroll
            for (int half = 0; half < 2; half++) {
                int r = rt * 16 + gid + half * 8;
                float g0 = c[rt][ct][half * 2],     u0 = c[rt][ct + 2][half * 2];
                float g1 = c[rt][ct][half * 2 + 1], u1 = c[rt][ct + 2][half * 2 + 1];
                float h0 = (g0 / (1.f + __expf(-g0))) * u0;
                float h1 = (g1 / (1.f + __expf(-g1))) * u1;
                size_t gidx = is_shared
                    ? (size_t)(m0 + r) * SINTER + col
                    : ((size_t)e * T_TOK + m0 + r) * INTER + col;
                float* hb = is_shared ? g_hs : g_he;
                *(float2*)&hb[gidx] = make_float2(tf32f(h0), tf32f(h1));
            }
        }
    }
}

// ---------------- 4. expert down-projection: y = h @ w2^T(e) ----------------
// grid (16, NEXP, 2)
__global__ __launch_bounds__(256, 2) void down_mma(const float* __restrict__ w2)
{
    extern __shared__ float sm[];
    float* As = sm;                      // [2][64*AST] tf32 bits (h)
    float* Bs = sm + 2 * 64 * AST;       // [2][32*KNST] raw [k][n]

    const int e  = blockIdx.y;
    const int cnt = g_counts[e];
    const int m0 = blockIdx.x * 64;
    if (m0 >= cnt) return;
    const int mr = min(64, cnt - m0);
    const int n0 = blockIdx.z * 256;

    const int tid  = threadIdx.x;
    const int wid  = tid >> 5;
    const int lane = tid & 31;
    const int gid  = lane >> 2;
    const int l4   = lane & 3;

    __shared__ int   s_tok[64];
    __shared__ int   s_slot[64];
    __shared__ float s_w[64];
    if (tid < 64) {
        int mm = (tid < mr) ? tid : 0;
        s_tok[tid]  = g_tok[e * T_TOK + m0 + mm];
        s_slot[tid] = g_tslot[e * T_TOK + m0 + mm];
        s_w[tid]    = g_tw[e * T_TOK + m0 + mm];
    }

    const float* hbase  = g_he + ((size_t)e * T_TOK + m0) * INTER;
    const float* w2base = w2 + (size_t)e * INTER * DIM + n0;

    float c[4][4][4];
    #pragma unroll
    for (int i = 0; i < 4; i++)
        #pragma unroll
        for (int j = 0; j < 4; j++)
            #pragma unroll
            for (int q = 0; q < 4; q++) c[i][j][q] = 0.f;

    {   // preload chunk 0
        #pragma unroll
        for (int j = 0; j < 2; j++) {
            int idx = tid + 256 * j;
            int row = idx >> 3, col = (idx & 7) * 4;
            cp16(&As[row * AST + col], hbase + (size_t)row * INTER + col);
        }
        #pragma unroll
        for (int j = 0; j < 8; j++) {
            int idx = tid + 256 * j;
            int kr = idx >> 6, nc = (idx & 63) * 4;
            cp16(&Bs[kr * KNST + nc], w2base + (size_t)kr * DIM + nc);
        }
        cpcommit();
    }
    const int NCH = INTER / KC;
    for (int kc = 0; kc < NCH; kc++) {
        int st = kc & 1;
        cpwait<0>();
        __syncthreads();
        if (kc < NCH - 1) {
            int kb = (kc + 1) * KC;
            int sn = st ^ 1;
            #pragma unroll
            for (int j = 0; j < 2; j++) {
                int idx = tid + 256 * j;
                int row = idx >> 3, col = (idx & 7) * 4;
                cp16(&As[sn * 64 * AST + row * AST + col],
                     hbase + (size_t)row * INTER + kb + col);
            }
            #pragma unroll
            for (int j = 0; j < 8; j++) {
                int idx = tid + 256 * j;
                int kr = idx >> 6, nc = (idx & 63) * 4;
                cp16(&Bs[sn * 32 * KNST + kr * KNST + nc],
                     w2base + (size_t)(kb + kr) * DIM + nc);
            }
            cpcommit();
        }
        const float* Asb = As + st * 64 * AST;
        const float* Bsb = Bs + st * 32 * KNST;
        #pragma unroll
        for (int ks = 0; ks < 4; ks++) {
            uint32_t ah[4][4];
            #pragma unroll
            for (int rt = 0; rt < 4; rt++) {
                int r0 = rt * 16 + gid;
                int cc = ks * 8 + l4;
                ah[rt][0] = __float_as_uint(Asb[r0 * AST + cc]);
                ah[rt][1] = __float_as_uint(Asb[(r0 + 8) * AST + cc]);
                ah[rt][2] = __float_as_uint(Asb[r0 * AST + cc + 4]);
                ah[rt][3] = __float_as_uint(Asb[(r0 + 8) * AST + cc + 4]);
            }
            uint32_t bh[4][2], bl[4][2];
            #pragma unroll
            for (int ct = 0; ct < 4; ct++) {
                int n = wid * 32 + ct * 8 + gid;
                split(Bsb[(ks * 8 + l4) * KNST + n],     bh[ct][0], bl[ct][0]);
                split(Bsb[(ks * 8 + l4 + 4) * KNST + n], bh[ct][1], bl[ct][1]);
            }
            #pragma unroll
            for (int ct = 0; ct < 4; ct++)
                #pragma unroll
                for (int rt = 0; rt < 4; rt++)
                    mma8(c[rt][ct], ah[rt], bh[ct][0], bh[ct][1]);
            #pragma unroll
            for (int ct = 0; ct < 4; ct++)
                #pragma unroll
                for (int rt = 0; rt < 4; rt++)
                    mma8(c[rt][ct], ah[rt], bl[ct][0], bl[ct][1]);
        }
    }

    #pragma unroll
    for (int rt = 0; rt < 4; rt++) {
        #pragma unroll
        for (int ct = 0; ct < 4; ct++) {
            int col = n0 + wid * 32 + ct * 8 + 2 * l4;
            #pragma unroll
            for (int half = 0; half < 2; half++) {
                int r = rt * 16 + gid + half * 8;
                if (r < mr) {
                    size_t base = ((size_t)(s_tok[r] * TOPK + s_slot[r])) * DIM + col;
                    float w = s_w[r];
                    *(float2*)&g_contrib[base] =
                        make_float2(w * c[rt][ct][half * 2], w * c[rt][ct][half * 2 + 1]);
                }
            }
        }
    }
}

// ---------------- 5. final GEMM split-K(8): part = H @ Wsd^T ----------------
__global__ __launch_bounds__(256, 2) void final_mma(const float* __restrict__ wsd)
{
    extern __shared__ float sm[];
    float* As = sm;                    // [2][64*AST] tf32 bits
    float* Bs = sm + 2 * 64 * AST;     // [2][256*BST] raw

    const int m0 = blockIdx.x * 64;
    const int n0 = blockIdx.y * 256;
    const int k0 = blockIdx.z * 128;
    const int tid  = threadIdx.x;
    const int wid  = tid >> 5;
    const int lane = tid & 31;
    const int gid  = lane >> 2;
    const int l4   = lane & 3;

    float c[4][4][4];
    #pragma unroll
    for (int i = 0; i < 4; i++)
        #pragma unroll
        for (int j = 0; j < 4; j++)
            #pragma unroll
            for (int q = 0; q < 4; q++) c[i][j][q] = 0.f;

    {
        #pragma unroll
        for (int j = 0; j < 2; j++) {
            int idx = tid + 256 * j;
            int row = idx >> 3, col = (idx & 7) * 4;
            cp16(&As[row * AST + col], g_hs + (size_t)(m0 + row) * SINTER + k0 + col);
        }
        #pragma unroll
        for (int j = 0; j < 8; j++) {
            int idx = tid + 256 * j;
            int row = idx >> 3, col = (idx & 7) * 4;
            cp16(&Bs[row * BST + col], wsd + (size_t)(n0 + row) * SINTER + k0 + col);
        }
        cpcommit();
    }
    const int NCH = 128 / KC;
    for (int kc = 0; kc < NCH; kc++) {
        int st = kc & 1;
        cpwait<0>();
        __syncthreads();
        if (kc < NCH - 1) {
            int kb = (kc + 1) * KC;
            int sn = st ^ 1;
            #pragma unroll
            for (int j = 0; j < 2; j++) {
                int idx = tid + 256 * j;
                int row = idx >> 3, col = (idx & 7) * 4;
                cp16(&As[sn * 64 * AST + row * AST + col],
                     g_hs + (size_t)(m0 + row) * SINTER + k0 + kb + col);
            }
            #pragma unroll
            for (int j = 0; j < 8; j++) {
                int idx = tid + 256 * j;
                int row = idx >> 3, col = (idx & 7) * 4;
                cp16(&Bs[sn * 256 * BST + row * BST + col],
                     wsd + (size_t)(n0 + row) * SINTER + k0 + kb + col);
            }
            cpcommit();
        }
        gemm_chunk2(As + st * 64 * AST, Bs + st * 256 * BST, wid, gid, l4, c);
    }

    #pragma unroll
    for (int rt = 0; rt < 4; rt++) {
        #pragma unroll
        for (int ct = 0; ct < 4; ct++) {
            int col = n0 + wid * 32 + ct * 8 + 2 * l4;
            int r0 = m0 + rt * 16 + gid, r1 = r0 + 8;
            *(float2*)&g_part[((size_t)blockIdx.z * T_TOK + r0) * DIM + col]
                = make_float2(c[rt][ct][0], c[rt][ct][1]);
            *(float2*)&g_part[((size_t)blockIdx.z * T_TOK + r1) * DIM + col]
                = make_float2(c[rt][ct][2], c[rt][ct][3]);
        }
    }
}

// ---------------- 6. reduce: out = sum parts + sum contribs ----------------
__global__ __launch_bounds__(256) void reduce_kernel(float* __restrict__ out)
{
    int t = blockIdx.x;
    #pragma unroll
    for (int h = 0; h < 2; h++) {
        int d = threadIdx.x + h * 256;
        float v = 0.f;
        #pragma unroll
        for (int z = 0; z < KSPLIT; z++)
            v += g_part[((size_t)z * T_TOK + t) * DIM + d];
        #pragma unroll
        for (int k = 0; k < TOPK; k++)
            v += g_contrib[((size_t)t * TOPK + k) * DIM + d];
        out[(size_t)t * DIM + d] = v;
    }
}

// ---------------- launcher ----------------
extern "C" void kernel_launch(void* const* d_in, const int* in_sizes, int n_in,
                              void* d_out, int out_size)
{
    const float* x   = (const float*)d_in[0];
    const float* wg  = (const float*)d_in[1];
    const float* w1  = (const float*)d_in[2];
    const float* w2  = (const float*)d_in[3];
    const float* w3  = (const float*)d_in[4];
    const float* wsg = (const float*)d_in[5];
    const float* wsu = (const float*)d_in[6];
    const float* wsd = (const float*)d_in[7];
    float* out = (float*)d_out;

    const int smem_up    = (2 * 64 * AST + 2 * 256 * BST) * 4;   // 92160
    const int smem_down  = (2 * 64 * AST + 2 * 32 * KNST) * 4;   // 86016
    const int smem_final = (2 * 64 * AST + 2 * 256 * BST) * 4;   // 92160

    cudaFuncSetAttribute(up_mma,    cudaFuncAttributeMaxDynamicSharedMemorySize, smem_up);
    cudaFuncSetAttribute(down_mma,  cudaFuncAttributeMaxDynamicSharedMemorySize, smem_down);
    cudaFuncSetAttribute(final_mma, cudaFuncAttributeMaxDynamicSharedMemorySize, smem_final);

    router_kernel<<<T_TOK / 16, 256>>>(x, wg);
    group_kernel<<<NEXP, 1024>>>();
    up_mma<<<dim3(16, NEXP * 2 + SINTER / 128), 256, smem_up>>>(x, w1, w3, wsg, wsu);
    down_mma<<<dim3(16, NEXP, 2), 256, smem_down>>>(w2);
    final_mma<<<dim3(16, 2, KSPLIT), 256, smem_final>>>(wsd);
    reduce_kernel<<<T_TOK, 256>>>(out);
}

// round 7
// speedup vs baseline: 3.1205x; 1.1262x over previous
#include <cuda_runtime.h>
#include <cuda_fp16.h>
#include <math.h>
#include <stdint.h>

#define T_TOK   1024
#define DIM     512
#define INTER   256
#define SINTER  1024
#define NEXP    64
#define TOPK    6
#define KC      32
#define AK2     20        // A plane row stride (uint32 = fp16x2), conflict-free
#define APLANE  (64 * AK2)
#define ABUF    (2 * APLANE)
#define BSTF    40        // B [n][k] row stride (floats), conflict-free
#define BBUF_UP (256 * BSTF)
#define KNST    260       // B [k][n] row stride (floats), conflict-free
#define BBUF_DN (32 * KNST)
#define KSPLIT  8

// ---------------- scratch (device globals; no allocation) ----------------
__device__ int      g_topk_idx[T_TOK * TOPK];
__device__ float    g_topk_w[T_TOK * TOPK];
__device__ int      g_counts[NEXP];
__device__ int      g_tok[NEXP * T_TOK];
__device__ int      g_tslot[NEXP * T_TOK];
__device__ float    g_tw[NEXP * T_TOK];
__device__ float    g_contrib[T_TOK * TOPK * DIM];        // 12.6 MB
__device__ float    g_part[KSPLIT * T_TOK * DIM];         // 16 MB
__device__ uint32_t g_he_hi[NEXP * T_TOK * (INTER / 2)];  // expert h hi plane
__device__ uint32_t g_he_lo[NEXP * T_TOK * (INTER / 2)];  // expert h lo plane
__device__ uint32_t g_hs_hi[T_TOK * (SINTER / 2)];        // shared h hi plane
__device__ uint32_t g_hs_lo[T_TOK * (SINTER / 2)];        // shared h lo plane

// ---------------- helpers ----------------
__device__ __forceinline__ void splitp(float2 v, uint32_t& hi, uint32_t& lo) {
    __half2 h = __floats2half2_rn(v.x, v.y);
    float2  b = __half22float2(h);
    __half2 l = __floats2half2_rn(v.x - b.x, v.y - b.y);
    hi = *reinterpret_cast<uint32_t*>(&h);
    lo = *reinterpret_cast<uint32_t*>(&l);
}
__device__ __forceinline__ void mma16(float c[4], const uint32_t a[4],
                                      uint32_t b0, uint32_t b1) {
    asm volatile(
        "mma.sync.aligned.m16n8k16.row.col.f32.f16.f16.f32 "
        "{%0,%1,%2,%3}, {%4,%5,%6,%7}, {%8,%9}, {%0,%1,%2,%3};"
        : "+f"(c[0]), "+f"(c[1]), "+f"(c[2]), "+f"(c[3])
        : "r"(a[0]), "r"(a[1]), "r"(a[2]), "r"(a[3]), "r"(b0), "r"(b1));
}
__device__ __forceinline__ void cp16(void* dst_smem, const void* src) {
    uint32_t d = (uint32_t)__cvta_generic_to_shared(dst_smem);
    asm volatile("cp.async.cg.shared.global [%0], [%1], 16;" :: "r"(d), "l"(src));
}
__device__ __forceinline__ void cpcommit() {
    asm volatile("cp.async.commit_group;" ::: "memory");
}
template <int N> __device__ __forceinline__ void cpwait() {
    asm volatile("cp.async.wait_group %0;" :: "n"(N) : "memory");
}

// 64x256xKC chunk, 3-term fp16 (hh, hl, lh). A planes = fp16x2; B raw fp32 [n][BSTF].
__device__ __forceinline__ void gemm16_nk(const uint32_t* __restrict__ Ah,
                                          const uint32_t* __restrict__ Al,
                                          const float* __restrict__ Bsb,
                                          const int nn[4], int gid, int l4,
                                          float c[4][4][4]) {
    #pragma unroll
    for (int ks = 0; ks < 2; ks++) {
        uint32_t bh[4][2], bl[4][2];
        #pragma unroll
        for (int ct = 0; ct < 4; ct++) {
            const float* bp = Bsb + nn[ct] * BSTF + ks * 16 + 2 * l4;
            splitp(*(const float2*)bp,       bh[ct][0], bl[ct][0]);
            splitp(*(const float2*)(bp + 8), bh[ct][1], bl[ct][1]);
        }
        uint32_t ah[4][4];
        #pragma unroll
        for (int rt = 0; rt < 4; rt++) {
            int r0 = rt * 16 + gid, cc = ks * 8 + l4;
            ah[rt][0] = Ah[r0 * AK2 + cc];
            ah[rt][1] = Ah[(r0 + 8) * AK2 + cc];
            ah[rt][2] = Ah[r0 * AK2 + cc + 4];
            ah[rt][3] = Ah[(r0 + 8) * AK2 + cc + 4];
        }
        #pragma unroll
        for (int ct = 0; ct < 4; ct++)
            #pragma unroll
            for (int rt = 0; rt < 4; rt++)
                mma16(c[rt][ct], ah[rt], bh[ct][0], bh[ct][1]);
        #pragma unroll
        for (int ct = 0; ct < 4; ct++)
            #pragma unroll
            for (int rt = 0; rt < 4; rt++)
                mma16(c[rt][ct], ah[rt], bl[ct][0], bl[ct][1]);
        uint32_t al[4][4];
        #pragma unroll
        for (int rt = 0; rt < 4; rt++) {
            int r0 = rt * 16 + gid, cc = ks * 8 + l4;
            al[rt][0] = Al[r0 * AK2 + cc];
            al[rt][1] = Al[(r0 + 8) * AK2 + cc];
            al[rt][2] = Al[r0 * AK2 + cc + 4];
            al[rt][3] = Al[(r0 + 8) * AK2 + cc + 4];
        }
        #pragma unroll
        for (int ct = 0; ct < 4; ct++)
            #pragma unroll
            for (int rt = 0; rt < 4; rt++)
                mma16(c[rt][ct], al[rt], bh[ct][0], bh[ct][1]);
    }
}

// Same but B raw fp32 [k][KNST] layout (down-proj).
__device__ __forceinline__ void gemm16_kn(const uint32_t* __restrict__ Ah,
                                          const uint32_t* __restrict__ Al,
                                          const float* __restrict__ Bsb,
                                          const int nn[4], int gid, int l4,
                                          float c[4][4][4]) {
    #pragma unroll
    for (int ks = 0; ks < 2; ks++) {
        uint32_t bh[4][2], bl[4][2];
        #pragma unroll
        for (int ct = 0; ct < 4; ct++) {
            int n = nn[ct];
            int kk = ks * 16 + 2 * l4;
            float f0 = Bsb[kk * KNST + n];
            float f1 = Bsb[(kk + 1) * KNST + n];
            splitp(make_float2(f0, f1), bh[ct][0], bl[ct][0]);
            float f2 = Bsb[(kk + 8) * KNST + n];
            float f3 = Bsb[(kk + 9) * KNST + n];
            splitp(make_float2(f2, f3), bh[ct][1], bl[ct][1]);
        }
        uint32_t ah[4][4];
        #pragma unroll
        for (int rt = 0; rt < 4; rt++) {
            int r0 = rt * 16 + gid, cc = ks * 8 + l4;
            ah[rt][0] = Ah[r0 * AK2 + cc];
            ah[rt][1] = Ah[(r0 + 8) * AK2 + cc];
            ah[rt][2] = Ah[r0 * AK2 + cc + 4];
            ah[rt][3] = Ah[(r0 + 8) * AK2 + cc + 4];
        }
        #pragma unroll
        for (int ct = 0; ct < 4; ct++)
            #pragma unroll
            for (int rt = 0; rt < 4; rt++)
                mma16(c[rt][ct], ah[rt], bh[ct][0], bh[ct][1]);
        #pragma unroll
        for (int ct = 0; ct < 4; ct++)
            #pragma unroll
            for (int rt = 0; rt < 4; rt++)
                mma16(c[rt][ct], ah[rt], bl[ct][0], bl[ct][1]);
        uint32_t al[4][4];
        #pragma unroll
        for (int rt = 0; rt < 4; rt++) {
            int r0 = rt * 16 + gid, cc = ks * 8 + l4;
            al[rt][0] = Al[r0 * AK2 + cc];
            al[rt][1] = Al[(r0 + 8) * AK2 + cc];
            al[rt][2] = Al[r0 * AK2 + cc + 4];
            al[rt][3] = Al[(r0 + 8) * AK2 + cc + 4];
        }
        #pragma unroll
        for (int ct = 0; ct < 4; ct++)
            #pragma unroll
            for (int rt = 0; rt < 4; rt++)
                mma16(c[rt][ct], al[rt], bh[ct][0], bh[ct][1]);
    }
}

// ---------------- 1. router ----------------
__global__ __launch_bounds__(256) void router_kernel(
    const float* __restrict__ x, const float* __restrict__ wg)
{
    const int t0  = blockIdx.x * 16;
    const int tid = threadIdx.x;
    __shared__ float xs[16 * DIM];
    __shared__ float sc[16 * NEXP];

    for (int idx = tid; idx < 16 * DIM / 4; idx += 256)
        *(float4*)&xs[idx * 4] = *(const float4*)&x[(size_t)t0 * DIM + idx * 4];
    __syncthreads();

    int e  = tid & 63;
    int tg = tid >> 6;
    const float4* wr = (const float4*)(wg + (size_t)e * DIM);
    for (int tt = tg; tt < 16; tt += 4) {
        float acc = 0.f;
        #pragma unroll 4
        for (int d4 = 0; d4 < DIM / 4; d4++) {
            float4 w  = wr[d4];
            float4 xv = *(const float4*)&xs[tt * DIM + d4 * 4];
            acc = fmaf(w.x, xv.x, fmaf(w.y, xv.y, fmaf(w.z, xv.z, fmaf(w.w, xv.w, acc))));
        }
        sc[tt * NEXP + e] = acc;
    }
    __syncthreads();

    if (tid < 16) {
        float* s = &sc[tid * NEXP];
        float vals[TOPK]; int idx[TOPK];
        for (int k = 0; k < TOPK; k++) {
            float best = -INFINITY; int bi = 0;
            for (int ee = 0; ee < NEXP; ee++)
                if (s[ee] > best) { best = s[ee]; bi = ee; }
            vals[k] = best; idx[k] = bi; s[bi] = -INFINITY;
        }
        float mx = vals[0];
        float w6[TOPK]; float sum = 0.f;
        #pragma unroll
        for (int k = 0; k < TOPK; k++) { w6[k] = __expf(vals[k] - mx); sum += w6[k]; }
        float inv = 1.f / sum;
        int t = t0 + tid;
        #pragma unroll
        for (int k = 0; k < TOPK; k++) {
            g_topk_idx[t * TOPK + k] = idx[k];
            g_topk_w[t * TOPK + k]   = w6[k] * inv;
        }
    }
}

// ---------------- 2. deterministic grouping ----------------
__global__ __launch_bounds__(1024) void group_kernel()
{
    int e = blockIdx.x;
    int t = threadIdx.x;
    int slot = -1;
    #pragma unroll
    for (int k = 0; k < TOPK; k++)
        if (g_topk_idx[t * TOPK + k] == e) slot = k;
    int flag = (slot >= 0) ? 1 : 0;

    __shared__ int sc[T_TOK];
    sc[t] = flag;
    __syncthreads();
    for (int off = 1; off < T_TOK; off <<= 1) {
        int v = (t >= off) ? sc[t - off] : 0;
        __syncthreads();
        sc[t] += v;
        __syncthreads();
    }
    if (flag) {
        int pos = sc[t] - 1;
        g_tok[e * T_TOK + pos]   = t;
        g_tslot[e * T_TOK + pos] = slot;
        g_tw[e * T_TOK + pos]    = g_topk_w[t * TOPK + slot];
    }
    if (t == T_TOK - 1) g_counts[e] = sc[T_TOK - 1];
}

// ---------------- 3. fused gate+up projection (experts + shared) ----------
// grid (16, NEXP*2 + SINTER/128)
__global__ __launch_bounds__(256, 2) void up_mma(
    const float* __restrict__ x,
    const float* __restrict__ w1, const float* __restrict__ w3,
    const float* __restrict__ wsg, const float* __restrict__ wsu)
{
    extern __shared__ float smf[];
    uint32_t* Au = (uint32_t*)smf;               // [2 buf][2 plane][64][AK2]
    float*    Bs = smf + 2 * ABUF;               // [2 buf][256][BSTF] raw fp32

    const int by = blockIdx.y;
    const bool is_shared = (by >= NEXP * 2);
    const int tid  = threadIdx.x;
    const int wid  = tid >> 5;
    const int lane = tid & 31;
    const int gid  = lane >> 2;
    const int l4   = lane & 3;
    const int m0   = blockIdx.x * 64;

    __shared__ int s_row[64];

    const float *Wg, *Wu;
    int e = 0, ncol0 = 0;
    if (is_shared) {
        int js = by - NEXP * 2;
        ncol0 = js * 128;
        Wg = wsg + (size_t)ncol0 * DIM;
        Wu = wsu + (size_t)ncol0 * DIM;
        if (tid < 64) s_row[tid] = m0 + tid;
    } else {
        e = by >> 1;
        int cnt = g_counts[e];
        if (m0 >= cnt) return;
        int mr = min(64, cnt - m0);
        int j  = by & 1;
        ncol0 = j * 128;
        Wg = w1 + (size_t)e * INTER * DIM + (size_t)ncol0 * DIM;
        Wu = w3 + (size_t)e * INTER * DIM + (size_t)ncol0 * DIM;
        if (tid < 64) s_row[tid] = g_tok[e * T_TOK + m0 + ((tid < mr) ? tid : 0)];
    }
    __syncthreads();

    const int ar  = tid >> 2;              // staging row
    const int acb = (tid & 3) * 4;         // k2 base of this thread's 8 floats
    const float* xrow = x + (size_t)s_row[ar] * DIM;

    const int nn[4] = { wid * 16 + gid, wid * 16 + 8 + gid,
                        128 + wid * 16 + gid, 128 + wid * 16 + 8 + gid };

    float c[4][4][4];   // ct 0..1 = gate cols, ct 2..3 = up cols
    #pragma unroll
    for (int i = 0; i < 4; i++)
        #pragma unroll
        for (int j = 0; j < 4; j++)
            #pragma unroll
            for (int q = 0; q < 4; q++) c[i][j][q] = 0.f;

    // preload chunk 0: A to regs, B via cp.async
    float4 pa0 = *(const float4*)(xrow + acb * 2);
    float4 pa1 = *(const float4*)(xrow + acb * 2 + 4);
    #pragma unroll
    for (int j = 0; j < 8; j++) {
        int idx = tid + 256 * j;
        int row = idx >> 3, col = (idx & 7) * 4;
        const float* src = (row < 128) ? (Wg + (size_t)row * DIM + col)
                                       : (Wu + (size_t)(row - 128) * DIM + col);
        cp16(&Bs[row * BSTF + col], src);
    }
    cpcommit();

    const int NCH = DIM / KC;   // 16
    for (int kc = 0; kc < NCH; kc++) {
        int st = kc & 1;
        {   // stage A chunk kc as fp16 planes
            uint32_t h0, l0, h1, l1, h2, l2, h3, l3;
            splitp(make_float2(pa0.x, pa0.y), h0, l0);
            splitp(make_float2(pa0.z, pa0.w), h1, l1);
            splitp(make_float2(pa1.x, pa1.y), h2, l2);
            splitp(make_float2(pa1.z, pa1.w), h3, l3);
            uint32_t* d = Au + st * ABUF + ar * AK2 + acb;
            *(uint4*)d            = make_uint4(h0, h1, h2, h3);
            *(uint4*)(d + APLANE) = make_uint4(l0, l1, l2, l3);
        }
        cpwait<0>();
        __syncthreads();
        if (kc < NCH - 1) {
            int kb = (kc + 1) * KC;
            int sn = st ^ 1;
            pa0 = *(const float4*)(xrow + kb + acb * 2);
            pa1 = *(const float4*)(xrow + kb + acb * 2 + 4);
            #pragma unroll
            for (int j = 0; j < 8; j++) {
                int idx = tid + 256 * j;
                int row = idx >> 3, col = (idx & 7) * 4;
                const float* src = (row < 128) ? (Wg + (size_t)row * DIM + kb + col)
                                               : (Wu + (size_t)(row - 128) * DIM + kb + col);
                cp16(&Bs[sn * BBUF_UP + row * BSTF + col], src);
            }
            cpcommit();
        }
        gemm16_nk(Au + st * ABUF, Au + st * ABUF + APLANE,
                  Bs + st * BBUF_UP, nn, gid, l4, c);
    }

    // epilogue: h = silu(gate)*up in regs -> fp16 planes -> global
    #pragma unroll
    for (int rt = 0; rt < 4; rt++) {
        #pragma unroll
        for (int ct = 0; ct < 2; ct++) {
            int col = ncol0 + wid * 16 + ct * 8 + 2 * l4;
            #pragma unroll
            for (int half = 0; half < 2; half++) {
                int r = rt * 16 + gid + half * 8;
                float g0 = c[rt][ct][half * 2],     u0 = c[rt][ct + 2][half * 2];
                float g1 = c[rt][ct][half * 2 + 1], u1 = c[rt][ct + 2][half * 2 + 1];
                float h0 = (g0 / (1.f + __expf(-g0))) * u0;
                float h1 = (g1 / (1.f + __expf(-g1))) * u1;
                uint32_t hh, hl;
                splitp(make_float2(h0, h1), hh, hl);
                if (is_shared) {
                    size_t gi = (size_t)(m0 + r) * (SINTER / 2) + (col >> 1);
                    g_hs_hi[gi] = hh; g_hs_lo[gi] = hl;
                } else {
                    size_t gi = ((size_t)e * T_TOK + m0 + r) * (INTER / 2) + (col >> 1);
                    g_he_hi[gi] = hh; g_he_lo[gi] = hl;
                }
            }
        }
    }
}

// ---------------- 4. expert down-projection ----------------
// grid (16, NEXP, 2)
__global__ __launch_bounds__(256, 2) void down_mma(const float* __restrict__ w2)
{
    extern __shared__ float smf[];
    uint32_t* Au = (uint32_t*)smf;               // [2][2 plane][64][AK2]
    float*    Bs = smf + 2 * ABUF;               // [2][32][KNST] raw [k][n]

    const int e  = blockIdx.y;
    const int cnt = g_counts[e];
    const int m0 = blockIdx.x * 64;
    if (m0 >= cnt) return;
    const int mr = min(64, cnt - m0);
    const int n0 = blockIdx.z * 256;

    const int tid  = threadIdx.x;
    const int wid  = tid >> 5;
    const int lane = tid & 31;
    const int gid  = lane >> 2;
    const int l4   = lane & 3;

    __shared__ int   s_tok[64];
    __shared__ int   s_slot[64];
    __shared__ float s_w[64];
    if (tid < 64) {
        int mm = (tid < mr) ? tid : 0;
        s_tok[tid]  = g_tok[e * T_TOK + m0 + mm];
        s_slot[tid] = g_tslot[e * T_TOK + m0 + mm];
        s_w[tid]    = g_tw[e * T_TOK + m0 + mm];
    }

    const uint32_t* hhi = g_he_hi + ((size_t)e * T_TOK + m0) * (INTER / 2);
    const uint32_t* hlo = g_he_lo + ((size_t)e * T_TOK + m0) * (INTER / 2);
    const float* w2base = w2 + (size_t)e * INTER * DIM + n0;

    const int nn[4] = { wid * 32 + gid, wid * 32 + 8 + gid,
                        wid * 32 + 16 + gid, wid * 32 + 24 + gid };

    float c[4][4][4];
    #pragma unroll
    for (int i = 0; i < 4; i++)
        #pragma unroll
        for (int j = 0; j < 4; j++)
            #pragma unroll
            for (int q = 0; q < 4; q++) c[i][j][q] = 0.f;

    {   // preload chunk 0: A planes (16 u32/row each) + B
        #pragma unroll
        for (int j = 0; j < 2; j++) {
            int idx = tid + 256 * j;
            int plane = idx >> 8, rem = idx & 255;
            int row = rem >> 2, seg = (rem & 3) * 4;
            const uint32_t* src = (plane ? hlo : hhi) + (size_t)row * (INTER / 2) + seg;
            cp16(Au + plane * APLANE + row * AK2 + seg, src);
        }
        #pragma unroll
        for (int j = 0; j < 8; j++) {
            int idx = tid + 256 * j;
            int kr = idx >> 6, nc = (idx & 63) * 4;
            cp16(&Bs[kr * KNST + nc], w2base + (size_t)kr * DIM + nc);
        }
        cpcommit();
    }
    const int NCH = INTER / KC;   // 8
    for (int kc = 0; kc < NCH; kc++) {
        int st = kc & 1;
        cpwait<0>();
        __syncthreads();
        if (kc < NCH - 1) {
            int kb2 = (kc + 1) * 16;
            int kb  = (kc + 1) * KC;
            int sn = st ^ 1;
            #pragma unroll
            for (int j = 0; j < 2; j++) {
                int idx = tid + 256 * j;
                int plane = idx >> 8, rem = idx & 255;
                int row = rem >> 2, seg = (rem & 3) * 4;
                const uint32_t* src = (plane ? hlo : hhi) + (size_t)row * (INTER / 2) + kb2 + seg;
                cp16(Au + sn * ABUF + plane * APLANE + row * AK2 + seg, src);
            }
            #pragma unroll
            for (int j = 0; j < 8; j++) {
                int idx = tid + 256 * j;
                int kr = idx >> 6, nc = (idx & 63) * 4;
                cp16(&Bs[sn * BBUF_DN + kr * KNST + nc],
                     w2base + (size_t)(kb + kr) * DIM + nc);
            }
            cpcommit();
        }
        gemm16_kn(Au + st * ABUF, Au + st * ABUF + APLANE,
                  Bs + st * BBUF_DN, nn, gid, l4, c);
    }

    #pragma unroll
    for (int rt = 0; rt < 4; rt++) {
        #pragma unroll
        for (int ct = 0; ct < 4; ct++) {
            int col = n0 + wid * 32 + ct * 8 + 2 * l4;
            #pragma unroll
            for (int half = 0; half < 2; half++) {
                int r = rt * 16 + gid + half * 8;
                if (r < mr) {
                    size_t base = ((size_t)(s_tok[r] * TOPK + s_slot[r])) * DIM + col;
                    float w = s_w[r];
                    *(float2*)&g_contrib[base] =
                        make_float2(w * c[rt][ct][half * 2], w * c[rt][ct][half * 2 + 1]);
                }
            }
        }
    }
}

// ---------------- 5. final GEMM split-K(8): part = H @ Wsd^T ----------------
// grid (16, 2, KSPLIT)
__global__ __launch_bounds__(256, 2) void final_mma(const float* __restrict__ wsd)
{
    extern __shared__ float smf[];
    uint32_t* Au = (uint32_t*)smf;               // [2][2 plane][64][AK2]
    float*    Bs = smf + 2 * ABUF;               // [2][256][BSTF]

    const int m0 = blockIdx.x * 64;
    const int n0 = blockIdx.y * 256;
    const int k0 = blockIdx.z * 128;
    const int k02 = k0 / 2;
    const int tid  = threadIdx.x;
    const int wid  = tid >> 5;
    const int lane = tid & 31;
    const int gid  = lane >> 2;
    const int l4   = lane & 3;

    const int nn[4] = { wid * 32 + gid, wid * 32 + 8 + gid,
                        wid * 32 + 16 + gid, wid * 32 + 24 + gid };

    float c[4][4][4];
    #pragma unroll
    for (int i = 0; i < 4; i++)
        #pragma unroll
        for (int j = 0; j < 4; j++)
            #pragma unroll
            for (int q = 0; q < 4; q++) c[i][j][q] = 0.f;

    {   // preload chunk 0
        #pragma unroll
        for (int j = 0; j < 2; j++) {
            int idx = tid + 256 * j;
            int plane = idx >> 8, rem = idx & 255;
            int row = rem >> 2, seg = (rem & 3) * 4;
            const uint32_t* src = (plane ? g_hs_lo : g_hs_hi)
                                  + (size_t)(m0 + row) * (SINTER / 2) + k02 + seg;
            cp16(Au + plane * APLANE + row * AK2 + seg, src);
        }
        #pragma unroll
        for (int j = 0; j < 8; j++) {
            int idx = tid + 256 * j;
            int row = idx >> 3, col = (idx & 7) * 4;
            cp16(&Bs[row * BSTF + col], wsd + (size_t)(n0 + row) * SINTER + k0 + col);
        }
        cpcommit();
    }
    const int NCH = 128 / KC;   // 4
    for (int kc = 0; kc < NCH; kc++) {
        int st = kc & 1;
        cpwait<0>();
        __syncthreads();
        if (kc < NCH - 1) {
            int kb  = (kc + 1) * KC;
            int kb2 = (kc + 1) * 16;
            int sn = st ^ 1;
            #pragma unroll
            for (int j = 0; j < 2; j++) {
                int idx = tid + 256 * j;
                int plane = idx >> 8, rem = idx & 255;
                int row = rem >> 2, seg = (rem & 3) * 4;
                const uint32_t* src = (plane ? g_hs_lo : g_hs_hi)
                                      + (size_t)(m0 + row) * (SINTER / 2) + k02 + kb2 + seg;
                cp16(Au + sn * ABUF + plane * APLANE + row * AK2 + seg, src);
            }
            #pragma unroll
            for (int j = 0; j < 8; j++) {
                int idx = tid + 256 * j;
                int row = idx >> 3, col = (idx & 7) * 4;
                cp16(&Bs[sn * BBUF_UP + row * BSTF + col],
                     wsd + (size_t)(n0 + row) * SINTER + k0 + kb + col);
            }
            cpcommit();
        }
        gemm16_nk(Au + st * ABUF, Au + st * ABUF + APLANE,
                  Bs + st * BBUF_UP, nn, gid, l4, c);
    }

    #pragma unroll
    for (int rt = 0; rt < 4; rt++) {
        #pragma unroll
        for (int ct = 0; ct < 4; ct++) {
            int col = n0 + wid * 32 + ct * 8 + 2 * l4;
            int r0 = m0 + rt * 16 + gid, r1 = r0 + 8;
            *(float2*)&g_part[((size_t)blockIdx.z * T_TOK + r0) * DIM + col]
                = make_float2(c[rt][ct][0], c[rt][ct][1]);
            *(float2*)&g_part[((size_t)blockIdx.z * T_TOK + r1) * DIM + col]
                = make_float2(c[rt][ct][2], c[rt][ct][3]);
        }
    }
}

// ---------------- 6. reduce: out = sum parts + sum contribs ----------------
__global__ __launch_bounds__(256) void reduce_kernel(float* __restrict__ out)
{
    int t = blockIdx.x;
    #pragma unroll
    for (int h = 0; h < 2; h++) {
        int d = threadIdx.x + h * 256;
        float v = 0.f;
        #pragma unroll
        for (int z = 0; z < KSPLIT; z++)
            v += g_part[((size_t)z * T_TOK + t) * DIM + d];
        #pragma unroll
        for (int k = 0; k < TOPK; k++)
            v += g_contrib[((size_t)t * TOPK + k) * DIM + d];
        out[(size_t)t * DIM + d] = v;
    }
}

// ---------------- launcher ----------------
extern "C" void kernel_launch(void* const* d_in, const int* in_sizes, int n_in,
                              void* d_out, int out_size)
{
    const float* x   = (const float*)d_in[0];
    const float* wg  = (const float*)d_in[1];
    const float* w1  = (const float*)d_in[2];
    const float* w2  = (const float*)d_in[3];
    const float* w3  = (const float*)d_in[4];
    const float* wsg = (const float*)d_in[5];
    const float* wsu = (const float*)d_in[6];
    const float* wsd = (const float*)d_in[7];
    float* out = (float*)d_out;

    const int smem_up    = (2 * ABUF + 2 * BBUF_UP) * 4;  // 20480 + 81920 = 102400
    const int smem_down  = (2 * ABUF + 2 * BBUF_DN) * 4;  // 20480 + 66560 = 87040
    const int smem_final = (2 * ABUF + 2 * BBUF_UP) * 4;  // 102400

    cudaFuncSetAttribute(up_mma,    cudaFuncAttributeMaxDynamicSharedMemorySize, smem_up);
    cudaFuncSetAttribute(down_mma,  cudaFuncAttributeMaxDynamicSharedMemorySize, smem_down);
    cudaFuncSetAttribute(final_mma, cudaFuncAttributeMaxDynamicSharedMemorySize, smem_final);

    router_kernel<<<T_TOK / 16, 256>>>(x, wg);
    group_kernel<<<NEXP, 1024>>>();
    up_mma<<<dim3(16, NEXP * 2 + SINTER / 128), 256, smem_up>>>(x, w1, w3, wsg, wsu);
    down_mma<<<dim3(16, NEXP, 2), 256, smem_down>>>(w2);
    final_mma<<<dim3(16, 2, KSPLIT), 256, smem_final>>>(wsd);
    reduce_kernel<<<T_TOK, 256>>>(out);
}

// round 8
// speedup vs baseline: 3.4107x; 1.0930x over previous
#include <cuda_runtime.h>
#include <cuda_fp16.h>
#include <math.h>
#include <stdint.h>

#define T_TOK   1024
#define DIM     512
#define INTER   256
#define SINTER  1024
#define NEXP    64
#define TOPK    6
#define KC      32
#define AK2     20        // A plane row stride (uint32 = fp16x2), conflict-free
#define APLANE  (64 * AK2)
#define ABUF    (2 * APLANE)
#define BSTF    40        // B [n][k] row stride (floats), conflict-free
#define BBUF_UP (256 * BSTF)
#define KNST    260       // B [k][n] row stride (floats), conflict-free
#define BBUF_DN (32 * KNST)
#define KSPLIT  8

// ---------------- scratch (device globals; no allocation) ----------------
__device__ int      g_topk_idx[T_TOK * TOPK];
__device__ float    g_topk_w[T_TOK * TOPK];
__device__ int      g_counts[NEXP];
__device__ int      g_tok[NEXP * T_TOK];
__device__ int      g_tslot[NEXP * T_TOK];
__device__ float    g_tw[NEXP * T_TOK];
__device__ float    g_contrib[T_TOK * TOPK * DIM];        // 12.6 MB
__device__ float    g_part[KSPLIT * T_TOK * DIM];         // 16 MB
__device__ uint32_t g_he_hi[NEXP * T_TOK * (INTER / 2)];  // expert h hi plane
__device__ uint32_t g_he_lo[NEXP * T_TOK * (INTER / 2)];  // expert h lo plane
__device__ uint32_t g_hs_hi[T_TOK * (SINTER / 2)];        // shared h hi plane
__device__ uint32_t g_hs_lo[T_TOK * (SINTER / 2)];        // shared h lo plane

// ---------------- helpers ----------------
__device__ __forceinline__ void splitp(float2 v, uint32_t& hi, uint32_t& lo) {
    __half2 h = __floats2half2_rn(v.x, v.y);
    float2  b = __half22float2(h);
    __half2 l = __floats2half2_rn(v.x - b.x, v.y - b.y);
    hi = *reinterpret_cast<uint32_t*>(&h);
    lo = *reinterpret_cast<uint32_t*>(&l);
}
__device__ __forceinline__ uint32_t h2bits(float a, float b) {
    __half2 h = __floats2half2_rn(a, b);
    return *reinterpret_cast<uint32_t*>(&h);
}
__device__ __forceinline__ void mma16(float c[4], const uint32_t a[4],
                                      uint32_t b0, uint32_t b1) {
    asm volatile(
        "mma.sync.aligned.m16n8k16.row.col.f32.f16.f16.f32 "
        "{%0,%1,%2,%3}, {%4,%5,%6,%7}, {%8,%9}, {%0,%1,%2,%3};"
        : "+f"(c[0]), "+f"(c[1]), "+f"(c[2]), "+f"(c[3])
        : "r"(a[0]), "r"(a[1]), "r"(a[2]), "r"(a[3]), "r"(b0), "r"(b1));
}
__device__ __forceinline__ void cp16(void* dst_smem, const void* src) {
    uint32_t d = (uint32_t)__cvta_generic_to_shared(dst_smem);
    asm volatile("cp.async.cg.shared.global [%0], [%1], 16;" :: "r"(d), "l"(src));
}
__device__ __forceinline__ void cpcommit() {
    asm volatile("cp.async.commit_group;" ::: "memory");
}
template <int N> __device__ __forceinline__ void cpwait() {
    asm volatile("cp.async.wait_group %0;" :: "n"(N) : "memory");
}

// 64x256xKC chunk, 2-term fp16 (Ahi*Bhi + Alo*Bhi). B single-plane fp16 from raw fp32.
// B layout [n][BSTF] fp32.
__device__ __forceinline__ void gemm16_nk(const uint32_t* __restrict__ Ah,
                                          const uint32_t* __restrict__ Al,
                                          const float* __restrict__ Bsb,
                                          const int nn[4], int gid, int l4,
                                          float c[4][4][4]) {
    #pragma unroll
    for (int ks = 0; ks < 2; ks++) {
        uint32_t bh[4][2];
        #pragma unroll
        for (int ct = 0; ct < 4; ct++) {
            const float* bp = Bsb + nn[ct] * BSTF + ks * 16 + 2 * l4;
            float2 v0 = *(const float2*)bp;
            float2 v1 = *(const float2*)(bp + 8);
            bh[ct][0] = h2bits(v0.x, v0.y);
            bh[ct][1] = h2bits(v1.x, v1.y);
        }
        uint32_t ah[4][4];
        #pragma unroll
        for (int rt = 0; rt < 4; rt++) {
            int r0 = rt * 16 + gid, cc = ks * 8 + l4;
            ah[rt][0] = Ah[r0 * AK2 + cc];
            ah[rt][1] = Ah[(r0 + 8) * AK2 + cc];
            ah[rt][2] = Ah[r0 * AK2 + cc + 4];
            ah[rt][3] = Ah[(r0 + 8) * AK2 + cc + 4];
        }
        #pragma unroll
        for (int ct = 0; ct < 4; ct++)
            #pragma unroll
            for (int rt = 0; rt < 4; rt++)
                mma16(c[rt][ct], ah[rt], bh[ct][0], bh[ct][1]);
        uint32_t al[4][4];
        #pragma unroll
        for (int rt = 0; rt < 4; rt++) {
            int r0 = rt * 16 + gid, cc = ks * 8 + l4;
            al[rt][0] = Al[r0 * AK2 + cc];
            al[rt][1] = Al[(r0 + 8) * AK2 + cc];
            al[rt][2] = Al[r0 * AK2 + cc + 4];
            al[rt][3] = Al[(r0 + 8) * AK2 + cc + 4];
        }
        #pragma unroll
        for (int ct = 0; ct < 4; ct++)
            #pragma unroll
            for (int rt = 0; rt < 4; rt++)
                mma16(c[rt][ct], al[rt], bh[ct][0], bh[ct][1]);
    }
}

// Same but B raw fp32 [k][KNST] layout (down-proj).
__device__ __forceinline__ void gemm16_kn(const uint32_t* __restrict__ Ah,
                                          const uint32_t* __restrict__ Al,
                                          const float* __restrict__ Bsb,
                                          const int nn[4], int gid, int l4,
                                          float c[4][4][4]) {
    #pragma unroll
    for (int ks = 0; ks < 2; ks++) {
        uint32_t bh[4][2];
        #pragma unroll
        for (int ct = 0; ct < 4; ct++) {
            int n = nn[ct];
            int kk = ks * 16 + 2 * l4;
            bh[ct][0] = h2bits(Bsb[kk * KNST + n],       Bsb[(kk + 1) * KNST + n]);
            bh[ct][1] = h2bits(Bsb[(kk + 8) * KNST + n], Bsb[(kk + 9) * KNST + n]);
        }
        uint32_t ah[4][4];
        #pragma unroll
        for (int rt = 0; rt < 4; rt++) {
            int r0 = rt * 16 + gid, cc = ks * 8 + l4;
            ah[rt][0] = Ah[r0 * AK2 + cc];
            ah[rt][1] = Ah[(r0 + 8) * AK2 + cc];
            ah[rt][2] = Ah[r0 * AK2 + cc + 4];
            ah[rt][3] = Ah[(r0 + 8) * AK2 + cc + 4];
        }
        #pragma unroll
        for (int ct = 0; ct < 4; ct++)
            #pragma unroll
            for (int rt = 0; rt < 4; rt++)
                mma16(c[rt][ct], ah[rt], bh[ct][0], bh[ct][1]);
        uint32_t al[4][4];
        #pragma unroll
        for (int rt = 0; rt < 4; rt++) {
            int r0 = rt * 16 + gid, cc = ks * 8 + l4;
            al[rt][0] = Al[r0 * AK2 + cc];
            al[rt][1] = Al[(r0 + 8) * AK2 + cc];
            al[rt][2] = Al[r0 * AK2 + cc + 4];
            al[rt][3] = Al[(r0 + 8) * AK2 + cc + 4];
        }
        #pragma unroll
        for (int ct = 0; ct < 4; ct++)
            #pragma unroll
            for (int rt = 0; rt < 4; rt++)
                mma16(c[rt][ct], al[rt], bh[ct][0], bh[ct][1]);
    }
}

// ---------------- 1. router ----------------
__global__ __launch_bounds__(256) void router_kernel(
    const float* __restrict__ x, const float* __restrict__ wg)
{
    const int t0  = blockIdx.x * 16;
    const int tid = threadIdx.x;
    __shared__ float xs[16 * DIM];
    __shared__ float sc[16 * NEXP];

    for (int idx = tid; idx < 16 * DIM / 4; idx += 256)
        *(float4*)&xs[idx * 4] = *(const float4*)&x[(size_t)t0 * DIM + idx * 4];
    __syncthreads();

    int e  = tid & 63;
    int tg = tid >> 6;
    const float4* wr = (const float4*)(wg + (size_t)e * DIM);
    for (int tt = tg; tt < 16; tt += 4) {
        float acc = 0.f;
        #pragma unroll 4
        for (int d4 = 0; d4 < DIM / 4; d4++) {
            float4 w  = wr[d4];
            float4 xv = *(const float4*)&xs[tt * DIM + d4 * 4];
            acc = fmaf(w.x, xv.x, fmaf(w.y, xv.y, fmaf(w.z, xv.z, fmaf(w.w, xv.w, acc))));
        }
        sc[tt * NEXP + e] = acc;
    }
    __syncthreads();

    if (tid < 16) {
        float* s = &sc[tid * NEXP];
        float vals[TOPK]; int idx[TOPK];
        for (int k = 0; k < TOPK; k++) {
            float best = -INFINITY; int bi = 0;
            for (int ee = 0; ee < NEXP; ee++)
                if (s[ee] > best) { best = s[ee]; bi = ee; }
            vals[k] = best; idx[k] = bi; s[bi] = -INFINITY;
        }
        float mx = vals[0];
        float w6[TOPK]; float sum = 0.f;
        #pragma unroll
        for (int k = 0; k < TOPK; k++) { w6[k] = __expf(vals[k] - mx); sum += w6[k]; }
        float inv = 1.f / sum;
        int t = t0 + tid;
        #pragma unroll
        for (int k = 0; k < TOPK; k++) {
            g_topk_idx[t * TOPK + k] = idx[k];
            g_topk_w[t * TOPK + k]   = w6[k] * inv;
        }
    }
}

// ---------------- 2. deterministic grouping ----------------
__global__ __launch_bounds__(1024) void group_kernel()
{
    int e = blockIdx.x;
    int t = threadIdx.x;
    int slot = -1;
    #pragma unroll
    for (int k = 0; k < TOPK; k++)
        if (g_topk_idx[t * TOPK + k] == e) slot = k;
    int flag = (slot >= 0) ? 1 : 0;

    __shared__ int sc[T_TOK];
    sc[t] = flag;
    __syncthreads();
    for (int off = 1; off < T_TOK; off <<= 1) {
        int v = (t >= off) ? sc[t - off] : 0;
        __syncthreads();
        sc[t] += v;
        __syncthreads();
    }
    if (flag) {
        int pos = sc[t] - 1;
        g_tok[e * T_TOK + pos]   = t;
        g_tslot[e * T_TOK + pos] = slot;
        g_tw[e * T_TOK + pos]    = g_topk_w[t * TOPK + slot];
    }
    if (t == T_TOK - 1) g_counts[e] = sc[T_TOK - 1];
}

// ---------------- 3. fused gate+up projection (experts + shared) ----------
// grid (16, NEXP*2 + SINTER/128)
__global__ __launch_bounds__(256, 2) void up_mma(
    const float* __restrict__ x,
    const float* __restrict__ w1, const float* __restrict__ w3,
    const float* __restrict__ wsg, const float* __restrict__ wsu)
{
    extern __shared__ float smf[];
    uint32_t* Au = (uint32_t*)smf;               // [2 buf][2 plane][64][AK2]
    float*    Bs = smf + 2 * ABUF;               // [2 buf][256][BSTF] raw fp32

    const int by = blockIdx.y;
    const bool is_shared = (by >= NEXP * 2);
    const int tid  = threadIdx.x;
    const int wid  = tid >> 5;
    const int lane = tid & 31;
    const int gid  = lane >> 2;
    const int l4   = lane & 3;
    const int m0   = blockIdx.x * 64;

    __shared__ int s_row[64];

    const float *Wg, *Wu;
    int e = 0, ncol0 = 0;
    if (is_shared) {
        int js = by - NEXP * 2;
        ncol0 = js * 128;
        Wg = wsg + (size_t)ncol0 * DIM;
        Wu = wsu + (size_t)ncol0 * DIM;
        if (tid < 64) s_row[tid] = m0 + tid;
    } else {
        e = by >> 1;
        int cnt = g_counts[e];
        if (m0 >= cnt) return;
        int mr = min(64, cnt - m0);
        int j  = by & 1;
        ncol0 = j * 128;
        Wg = w1 + (size_t)e * INTER * DIM + (size_t)ncol0 * DIM;
        Wu = w3 + (size_t)e * INTER * DIM + (size_t)ncol0 * DIM;
        if (tid < 64) s_row[tid] = g_tok[e * T_TOK + m0 + ((tid < mr) ? tid : 0)];
    }
    __syncthreads();

    const int ar  = tid >> 2;
    const int acb = (tid & 3) * 4;
    const float* xrow = x + (size_t)s_row[ar] * DIM;

    const int nn[4] = { wid * 16 + gid, wid * 16 + 8 + gid,
                        128 + wid * 16 + gid, 128 + wid * 16 + 8 + gid };

    float c[4][4][4];   // ct 0..1 = gate cols, ct 2..3 = up cols
    #pragma unroll
    for (int i = 0; i < 4; i++)
        #pragma unroll
        for (int j = 0; j < 4; j++)
            #pragma unroll
            for (int q = 0; q < 4; q++) c[i][j][q] = 0.f;

    float4 pa0 = *(const float4*)(xrow + acb * 2);
    float4 pa1 = *(const float4*)(xrow + acb * 2 + 4);
    #pragma unroll
    for (int j = 0; j < 8; j++) {
        int idx = tid + 256 * j;
        int row = idx >> 3, col = (idx & 7) * 4;
        const float* src = (row < 128) ? (Wg + (size_t)row * DIM + col)
                                       : (Wu + (size_t)(row - 128) * DIM + col);
        cp16(&Bs[row * BSTF + col], src);
    }
    cpcommit();

    const int NCH = DIM / KC;   // 16
    for (int kc = 0; kc < NCH; kc++) {
        int st = kc & 1;
        {
            uint32_t h0, l0, h1, l1, h2, l2, h3, l3;
            splitp(make_float2(pa0.x, pa0.y), h0, l0);
            splitp(make_float2(pa0.z, pa0.w), h1, l1);
            splitp(make_float2(pa1.x, pa1.y), h2, l2);
            splitp(make_float2(pa1.z, pa1.w), h3, l3);
            uint32_t* d = Au + st * ABUF + ar * AK2 + acb;
            *(uint4*)d            = make_uint4(h0, h1, h2, h3);
            *(uint4*)(d + APLANE) = make_uint4(l0, l1, l2, l3);
        }
        cpwait<0>();
        __syncthreads();
        if (kc < NCH - 1) {
            int kb = (kc + 1) * KC;
            int sn = st ^ 1;
            pa0 = *(const float4*)(xrow + kb + acb * 2);
            pa1 = *(const float4*)(xrow + kb + acb * 2 + 4);
            #pragma unroll
            for (int j = 0; j < 8; j++) {
                int idx = tid + 256 * j;
                int row = idx >> 3, col = (idx & 7) * 4;
                const float* src = (row < 128) ? (Wg + (size_t)row * DIM + kb + col)
                                               : (Wu + (size_t)(row - 128) * DIM + kb + col);
                cp16(&Bs[sn * BBUF_UP + row * BSTF + col], src);
            }
            cpcommit();
        }
        gemm16_nk(Au + st * ABUF, Au + st * ABUF + APLANE,
                  Bs + st * BBUF_UP, nn, gid, l4, c);
    }

    // epilogue: h = silu(gate)*up in regs -> fp16 planes -> global
    #pragma unroll
    for (int rt = 0; rt < 4; rt++) {
        #pragma unroll
        for (int ct = 0; ct < 2; ct++) {
            int col = ncol0 + wid * 16 + ct * 8 + 2 * l4;
            #pragma unroll
            for (int half = 0; half < 2; half++) {
                int r = rt * 16 + gid + half * 8;
                float g0 = c[rt][ct][half * 2],     u0 = c[rt][ct + 2][half * 2];
                float g1 = c[rt][ct][half * 2 + 1], u1 = c[rt][ct + 2][half * 2 + 1];
                float h0 = (g0 / (1.f + __expf(-g0))) * u0;
                float h1 = (g1 / (1.f + __expf(-g1))) * u1;
                uint32_t hh, hl;
                splitp(make_float2(h0, h1), hh, hl);
                if (is_shared) {
                    size_t gi = (size_t)(m0 + r) * (SINTER / 2) + (col >> 1);
                    g_hs_hi[gi] = hh; g_hs_lo[gi] = hl;
                } else {
                    size_t gi = ((size_t)e * T_TOK + m0 + r) * (INTER / 2) + (col >> 1);
                    g_he_hi[gi] = hh; g_he_lo[gi] = hl;
                }
            }
        }
    }
}

// ---------------- 4. expert down-projection ----------------
// grid (16, NEXP, 2)
__global__ __launch_bounds__(256, 2) void down_mma(const float* __restrict__ w2)
{
    extern __shared__ float smf[];
    uint32_t* Au = (uint32_t*)smf;               // [2][2 plane][64][AK2]
    float*    Bs = smf + 2 * ABUF;               // [2][32][KNST] raw [k][n]

    const int e  = blockIdx.y;
    const int cnt = g_counts[e];
    const int m0 = blockIdx.x * 64;
    if (m0 >= cnt) return;
    const int mr = min(64, cnt - m0);
    const int n0 = blockIdx.z * 256;

    const int tid  = threadIdx.x;
    const int wid  = tid >> 5;
    const int lane = tid & 31;
    const int gid  = lane >> 2;
    const int l4   = lane & 3;

    __shared__ int   s_tok[64];
    __shared__ int   s_slot[64];
    __shared__ float s_w[64];
    if (tid < 64) {
        int mm = (tid < mr) ? tid : 0;
        s_tok[tid]  = g_tok[e * T_TOK + m0 + mm];
        s_slot[tid] = g_tslot[e * T_TOK + m0 + mm];
        s_w[tid]    = g_tw[e * T_TOK + m0 + mm];
    }

    const uint32_t* hhi = g_he_hi + ((size_t)e * T_TOK + m0) * (INTER / 2);
    const uint32_t* hlo = g_he_lo + ((size_t)e * T_TOK + m0) * (INTER / 2);
    const float* w2base = w2 + (size_t)e * INTER * DIM + n0;

    const int nn[4] = { wid * 32 + gid, wid * 32 + 8 + gid,
                        wid * 32 + 16 + gid, wid * 32 + 24 + gid };

    float c[4][4][4];
    #pragma unroll
    for (int i = 0; i < 4; i++)
        #pragma unroll
        for (int j = 0; j < 4; j++)
            #pragma unroll
            for (int q = 0; q < 4; q++) c[i][j][q] = 0.f;

    {
        #pragma unroll
        for (int j = 0; j < 2; j++) {
            int idx = tid + 256 * j;
            int plane = idx >> 8, rem = idx & 255;
            int row = rem >> 2, seg = (rem & 3) * 4;
            const uint32_t* src = (plane ? hlo : hhi) + (size_t)row * (INTER / 2) + seg;
            cp16(Au + plane * APLANE + row * AK2 + seg, src);
        }
        #pragma unroll
        for (int j = 0; j < 8; j++) {
            int idx = tid + 256 * j;
            int kr = idx >> 6, nc = (idx & 63) * 4;
            cp16(&Bs[kr * KNST + nc], w2base + (size_t)kr * DIM + nc);
        }
        cpcommit();
    }
    const int NCH = INTER / KC;   // 8
    for (int kc = 0; kc < NCH; kc++) {
        int st = kc & 1;
        cpwait<0>();
        __syncthreads();
        if (kc < NCH - 1) {
            int kb2 = (kc + 1) * 16;
            int kb  = (kc + 1) * KC;
            int sn = st ^ 1;
            #pragma unroll
            for (int j = 0; j < 2; j++) {
                int idx = tid + 256 * j;
                int plane = idx >> 8, rem = idx & 255;
                int row = rem >> 2, seg = (rem & 3) * 4;
                const uint32_t* src = (plane ? hlo : hhi) + (size_t)row * (INTER / 2) + kb2 + seg;
                cp16(Au + sn * ABUF + plane * APLANE + row * AK2 + seg, src);
            }
            #pragma unroll
            for (int j = 0; j < 8; j++) {
                int idx = tid + 256 * j;
                int kr = idx >> 6, nc = (idx & 63) * 4;
                cp16(&Bs[sn * BBUF_DN + kr * KNST + nc],
                     w2base + (size_t)(kb + kr) * DIM + nc);
            }
            cpcommit();
        }
        gemm16_kn(Au + st * ABUF, Au + st * ABUF + APLANE,
                  Bs + st * BBUF_DN, nn, gid, l4, c);
    }

    #pragma unroll
    for (int rt = 0; rt < 4; rt++) {
        #pragma unroll
        for (int ct = 0; ct < 4; ct++) {
            int col = n0 + wid * 32 + ct * 8 + 2 * l4;
            #pragma unroll
            for (int half = 0; half < 2; half++) {
                int r = rt * 16 + gid + half * 8;
                if (r < mr) {
                    size_t base = ((size_t)(s_tok[r] * TOPK + s_slot[r])) * DIM + col;
                    float w = s_w[r];
                    *(float2*)&g_contrib[base] =
                        make_float2(w * c[rt][ct][half * 2], w * c[rt][ct][half * 2 + 1]);
                }
            }
        }
    }
}

// ---------------- 5. final GEMM split-K(8): part = H @ Wsd^T ----------------
// grid (16, 2, KSPLIT)
__global__ __launch_bounds__(256, 2) void final_mma(const float* __restrict__ wsd)
{
    extern __shared__ float smf[];
    uint32_t* Au = (uint32_t*)smf;               // [2][2 plane][64][AK2]
    float*    Bs = smf + 2 * ABUF;               // [2][256][BSTF]

    const int m0 = blockIdx.x * 64;
    const int n0 = blockIdx.y * 256;
    const int k0 = blockIdx.z * 128;
    const int k02 = k0 / 2;
    const int tid  = threadIdx.x;
    const int wid  = tid >> 5;
    const int lane = tid & 31;
    const int gid  = lane >> 2;
    const int l4   = lane & 3;

    const int nn[4] = { wid * 32 + gid, wid * 32 + 8 + gid,
                        wid * 32 + 16 + gid, wid * 32 + 24 + gid };

    float c[4][4][4];
    #pragma unroll
    for (int i = 0; i < 4; i++)
        #pragma unroll
        for (int j = 0; j < 4; j++)
            #pragma unroll
            for (int q = 0; q < 4; q++) c[i][j][q] = 0.f;

    {
        #pragma unroll
        for (int j = 0; j < 2; j++) {
            int idx = tid + 256 * j;
            int plane = idx >> 8, rem = idx & 255;
            int row = rem >> 2, seg = (rem & 3) * 4;
            const uint32_t* src = (plane ? g_hs_lo : g_hs_hi)
                                  + (size_t)(m0 + row) * (SINTER / 2) + k02 + seg;
            cp16(Au + plane * APLANE + row * AK2 + seg, src);
        }
        #pragma unroll
        for (int j = 0; j < 8; j++) {
            int idx = tid + 256 * j;
            int row = idx >> 3, col = (idx & 7) * 4;
            cp16(&Bs[row * BSTF + col], wsd + (size_t)(n0 + row) * SINTER + k0 + col);
        }
        cpcommit();
    }
    const int NCH = 128 / KC;   // 4
    for (int kc = 0; kc < NCH; kc++) {
        int st = kc & 1;
        cpwait<0>();
        __syncthreads();
        if (kc < NCH - 1) {
            int kb  = (kc + 1) * KC;
            int kb2 = (kc + 1) * 16;
            int sn = st ^ 1;
            #pragma unroll
            for (int j = 0; j < 2; j++) {
                int idx = tid + 256 * j;
                int plane = idx >> 8, rem = idx & 255;
                int row = rem >> 2, seg = (rem & 3) * 4;
                const uint32_t* src = (plane ? g_hs_lo : g_hs_hi)
                                      + (size_t)(m0 + row) * (SINTER / 2) + k02 + kb2 + seg;
                cp16(Au + sn * ABUF + plane * APLANE + row * AK2 + seg, src);
            }
            #pragma unroll
            for (int j = 0; j < 8; j++) {
                int idx = tid + 256 * j;
                int row = idx >> 3, col = (idx & 7) * 4;
                cp16(&Bs[sn * BBUF_UP + row * BSTF + col],
                     wsd + (size_t)(n0 + row) * SINTER + k0 + kb + col);
            }
            cpcommit();
        }
        gemm16_nk(Au + st * ABUF, Au + st * ABUF + APLANE,
                  Bs + st * BBUF_UP, nn, gid, l4, c);
    }

    #pragma unroll
    for (int rt = 0; rt < 4; rt++) {
        #pragma unroll
        for (int ct = 0; ct < 4; ct++) {
            int col = n0 + wid * 32 + ct * 8 + 2 * l4;
            int r0 = m0 + rt * 16 + gid, r1 = r0 + 8;
            *(float2*)&g_part[((size_t)blockIdx.z * T_TOK + r0) * DIM + col]
                = make_float2(c[rt][ct][0], c[rt][ct][1]);
            *(float2*)&g_part[((size_t)blockIdx.z * T_TOK + r1) * DIM + col]
                = make_float2(c[rt][ct][2], c[rt][ct][3]);
        }
    }
}

// ---------------- 6. reduce: out = sum parts + sum contribs ----------------
__global__ __launch_bounds__(256) void reduce_kernel(float* __restrict__ out)
{
    int t = blockIdx.x;
    #pragma unroll
    for (int h = 0; h < 2; h++) {
        int d = threadIdx.x + h * 256;
        float v = 0.f;
        #pragma unroll
        for (int z = 0; z < KSPLIT; z++)
            v += g_part[((size_t)z * T_TOK + t) * DIM + d];
        #pragma unroll
        for (int k = 0; k < TOPK; k++)
            v += g_contrib[((size_t)t * TOPK + k) * DIM + d];
        out[(size_t)t * DIM + d] = v;
    }
}

// ---------------- launcher ----------------
extern "C" void kernel_launch(void* const* d_in, const int* in_sizes, int n_in,
                              void* d_out, int out_size)
{
    const float* x   = (const float*)d_in[0];
    const float* wg  = (const float*)d_in[1];
    const float* w1  = (const float*)d_in[2];
    const float* w2  = (const float*)d_in[3];
    const float* w3  = (const float*)d_in[4];
    const float* wsg = (const float*)d_in[5];
    const float* wsu = (const float*)d_in[6];
    const float* wsd = (const float*)d_in[7];
    float* out = (float*)d_out;

    const int smem_up    = (2 * ABUF + 2 * BBUF_UP) * 4;  // 102400
    const int smem_down  = (2 * ABUF + 2 * BBUF_DN) * 4;  // 87040
    const int smem_final = (2 * ABUF + 2 * BBUF_UP) * 4;  // 102400

    cudaFuncSetAttribute(up_mma,    cudaFuncAttributeMaxDynamicSharedMemorySize, smem_up);
    cudaFuncSetAttribute(down_mma,  cudaFuncAttributeMaxDynamicSharedMemorySize, smem_down);
    cudaFuncSetAttribute(final_mma, cudaFuncAttributeMaxDynamicSharedMemorySize, smem_final);

    router_kernel<<<T_TOK / 16, 256>>>(x, wg);
    group_kernel<<<NEXP, 1024>>>();
    up_mma<<<dim3(16, NEXP * 2 + SINTER / 128), 256, smem_up>>>(x, w1, w3, wsg, wsu);
    down_mma<<<dim3(16, NEXP, 2), 256, smem_down>>>(w2);
    final_mma<<<dim3(16, 2, KSPLIT), 256, smem_final>>>(wsd);
    reduce_kernel<<<T_TOK, 256>>>(out);
}